// round 7
// baseline (speedup 1.0000x reference)
#include <cuda_runtime.h>
#include <math.h>

#define NV 1024
#define NM 8192
#define DEG 8
#define SD 64
#define HD 128
#define NSTEPS 10

// ---------------- persistent device state ----------------
__device__ float g_hv[NM*SD];     // h_v2f
__device__ float g_hf[NM*SD];     // h_f2v
__device__ float g_P [NM*HD];
__device__ float g_Q [NM*HD];
__device__ int   g_varlist[NV*DEG];
__device__ int   g_cnt[NV];

__device__ __forceinline__ float sigm(float x) {
    return __fdividef(1.f, 1.f + __expf(-x));
}
__device__ __forceinline__ float tanh_fast(float x) {
    return 1.f - __fdividef(2.f, __expf(2.f*x) + 1.f);
}

// ---------------- init ----------------
__global__ void k_init_a() {
    int idx = blockIdx.x*blockDim.x + threadIdx.x;
    if (idx < NV) g_cnt[idx] = 0;
    if (idx < NM*SD) { g_hv[idx] = 0.f; g_hf[idx] = 0.f; }
}
__global__ void k_init_b(const int* __restrict__ node_var) {
    int m = blockIdx.x*blockDim.x + threadIdx.x;
    if (m >= NM) return;
    int u = node_var[m];
    int pos = atomicAdd(&g_cnt[u], 1);
    g_varlist[u*DEG + pos] = m;
}
__global__ void k_init_c() {
    int v = blockIdx.x*blockDim.x + threadIdx.x;
    if (v >= NV) return;
    int* p = &g_varlist[v*DEG];
    for (int a = 1; a < DEG; a++) {
        int key = p[a]; int b = a - 1;
        while (b >= 0 && p[b] > key) { p[b+1] = p[b]; b--; }
        p[b+1] = key;
    }
}

// ---------------- K1: P/Q precompute ----------------
// smem floats: sW1 16512 | shf 64*68 | shv 64*68 | sbv 64  = 25280
#define K1_SMEM (25280*4)
__global__ void __launch_bounds__(256) k1_pq(
    const float* __restrict__ W1, const float* __restrict__ b1,
    const float* __restrict__ bvec, const int* __restrict__ node_var)
{
    extern __shared__ float sm[];
    float* sW1 = sm;
    float* shf = sm + 16512;
    float* shv = sm + 20864;
    float* sbv = sm + 25216;
    int t = threadIdx.x;
    int mb = blockIdx.x * 64;
    for (int i = t; i < 16512; i += 256) sW1[i] = W1[i];
    for (int i = t; i < 4096; i += 256) {
        int n = i >> 6, k = i & 63;
        shf[k*68+n] = g_hf[(mb+n)*SD + k];
        shv[k*68+n] = g_hv[(mb+n)*SD + k];
    }
    if (t < 64) sbv[t] = bvec[node_var[mb+t]];
    __syncthreads();
    int col = t & 127, part = t >> 7;
    float rb1 = b1[col];
    float wlast = sW1[col*129 + 128];
    const float* hT = part ? shv : shf;
    const float* wrow = sW1 + col*129 + (part ? 64 : 0);
    float* dst = part ? g_Q : g_P;
    for (int nb = 0; nb < 64; nb += 32) {
        float acc[32];
        #pragma unroll
        for (int n = 0; n < 32; n++)
            acc[n] = part ? fmaf(sbv[nb+n], wlast, rb1) : 0.f;
        #pragma unroll 4
        for (int k = 0; k < 64; k++) {
            float w = wrow[k];
            const float4* hp = (const float4*)&hT[k*68 + nb];
            #pragma unroll
            for (int n4 = 0; n4 < 8; n4++) {
                float4 h4 = hp[n4];
                acc[n4*4+0] = fmaf(h4.x, w, acc[n4*4+0]);
                acc[n4*4+1] = fmaf(h4.y, w, acc[n4*4+1]);
                acc[n4*4+2] = fmaf(h4.z, w, acc[n4*4+2]);
                acc[n4*4+3] = fmaf(h4.w, w, acc[n4*4+3]);
            }
        }
        #pragma unroll
        for (int n = 0; n < 32; n++)
            dst[(mb+nb+n)*HD + col] = acc[n];
    }
}

// ---------------- K2: per-variable edge MLP + segsum + GRU(h_v2f) -------
// smem floats: sW2T 16512 | sP 1024 | sQ 1024 | l1T 1024 | snm 16 | sPart 64 = 19664
#define K2_SMEM (19664*4)
__global__ void __launch_bounds__(256) k2_edges(
    const float* __restrict__ W2, const float* __restrict__ b2v,
    const float* __restrict__ W3, const float* __restrict__ b3,
    const float* __restrict__ gWih, const float* __restrict__ gWhh,
    const float* __restrict__ gbih, const float* __restrict__ gbhh)
{
    extern __shared__ float sm[];
    __shared__ int smIdx[8];
    float* sW2T  = sm;
    float* sP    = sm + 16512;
    float* sQ    = sm + 17536;
    float* l1T   = sm + 18560;
    float* snm   = sm + 19584;
    float* sPart = sm + 19600;
    int t = threadIdx.x, v = blockIdx.x;
    if (t < 8) smIdx[t] = g_varlist[v*DEG + t];
    if (t >= 8 && t < 24) snm[t-8] = 0.f;
    for (int i = t; i < 16384; i += 256) {
        int c = i >> 7, k = i & 127;
        sW2T[k*129 + c] = W2[i];
    }
    __syncthreads();
    for (int i = t; i < 1024; i += 256) {
        int n = i >> 7;
        sP[i] = g_P[smIdx[n]*HD + (i & 127)];
        sQ[i] = g_Q[smIdx[n]*HD + (i & 127)];
    }
    __syncthreads();
    int col = t & 127, e0 = (t >> 7) * 4, wid = t >> 5, lane = t & 31;
    float rb2 = b2v[col], w30 = W3[col], w31 = W3[HD + col];
    for (int g = 0; g < 7; g++) {
        int ebase = g*8 + e0;
        float l1v[4];
        #pragma unroll
        for (int q = 0; q < 4; q++) {
            int e = ebase + q, ii = e/7, jj = e - ii*7;
            int j = jj + (jj >= ii);
            l1v[q] = fmaxf(sP[j*HD + col] + sQ[ii*HD + col], 0.f);
        }
        *(float4*)&l1T[col*8 + e0] = make_float4(l1v[0], l1v[1], l1v[2], l1v[3]);
        __syncthreads();
        float a0 = rb2, a1 = rb2, a2 = rb2, a3 = rb2;
        #pragma unroll 8
        for (int k = 0; k < 128; k++) {
            float ww = sW2T[k*129 + col];
            float4 L = *(const float4*)&l1T[k*8 + e0];
            a0 = fmaf(L.x, ww, a0); a1 = fmaf(L.y, ww, a1);
            a2 = fmaf(L.z, ww, a2); a3 = fmaf(L.w, ww, a3);
        }
        float av[4] = {a0, a1, a2, a3};
        #pragma unroll
        for (int q = 0; q < 4; q++) {
            float l2 = fmaxf(av[q], 0.f);
            float p0 = l2*w30, p1 = l2*w31;
            #pragma unroll
            for (int off = 16; off; off >>= 1) {
                p0 += __shfl_xor_sync(0xffffffffu, p0, off);
                p1 += __shfl_xor_sync(0xffffffffu, p1, off);
            }
            if (lane == 0) { sPart[(wid*4+q)*2] = p0; sPart[(wid*4+q)*2+1] = p1; }
        }
        __syncthreads();
        if (t < 2) {          // deterministic serial segment-sum
            int c = t;
            for (int el = 0; el < 8; el++) {
                int e = g*8 + el, ii = e/7;
                int q = el & 3, hw = (el >> 2) * 4;
                float s = sPart[((hw+0)*4+q)*2+c] + sPart[((hw+1)*4+q)*2+c]
                        + sPart[((hw+2)*4+q)*2+c] + sPart[((hw+3)*4+q)*2+c];
                snm[ii*2 + c] += s;
            }
        }
        __syncthreads();
    }
    // ---- GRU(h_v2f), weights overlay sW2T region
    float* sWhh = sm;            // 192*65 = 12480
    float* sWih = sm + 12480;    // 384
    float* sbih = sm + 12864;    // 192
    float* sbhh = sm + 13056;    // 192
    float* sHv  = sm + 16512;    // 8*65 (reuse sP)
    for (int i = t; i < 12288; i += 256) { int q = i >> 6, k = i & 63; sWhh[q*65+k] = gWhh[i]; }
    for (int i = t; i < 384; i += 256) sWih[i] = gWih[i];
    if (t < 192) { sbih[t] = gbih[t]; sbhh[t] = gbhh[t]; }
    for (int i = t; i < 512; i += 256) { int n = i >> 6, k = i & 63; sHv[n*65+k] = g_hv[smIdx[n]*SD+k]; }
    __syncthreads();
    float sb30 = 7.f*b3[0], sb31 = 7.f*b3[1];
    int nn = t >> 5, s0 = t & 31;
    float x0 = snm[nn*2] + sb30, x1 = snm[nn*2+1] + sb31;
    const float* hrow = sHv + nn*65;
    #pragma unroll
    for (int j2 = 0; j2 < 2; j2++) {
        int s = s0 + j2*32;
        float gir = fmaf(x1, sWih[2*s+1],       fmaf(x0, sWih[2*s],       sbih[s]));
        float giz = fmaf(x1, sWih[2*(64+s)+1],  fmaf(x0, sWih[2*(64+s)],  sbih[64+s]));
        float gin = fmaf(x1, sWih[2*(128+s)+1], fmaf(x0, sWih[2*(128+s)], sbih[128+s]));
        float ghr = sbhh[s], ghz = sbhh[64+s], ghn = sbhh[128+s];
        const float* wr = sWhh + s*65;
        const float* wz = sWhh + (64+s)*65;
        const float* wg = sWhh + (128+s)*65;
        #pragma unroll 8
        for (int k = 0; k < 64; k++) {
            float h = hrow[k];
            ghr = fmaf(h, wr[k], ghr);
            ghz = fmaf(h, wz[k], ghz);
            ghn = fmaf(h, wg[k], ghn);
        }
        float r  = sigm(gir + ghr);
        float z  = sigm(giz + ghz);
        float gg = tanh_fast(fmaf(r, ghn, gin));
        float h  = hrow[s];
        g_hv[smIdx[nn]*SD + s] = fmaf(z, h - gg, gg);
    }
}

// ---------------- K3: f2v MLP + logsumexp + GRU(h_f2v) ----------------
// smem floats: sW 16772 | sXT 130*36 | l1T 128*36 | sAB 64 | sEm 64 | sNew 64 | sPart 64 = 26316
#define K3_SMEM (26316*4)
__global__ void __launch_bounds__(256) k3_f2v(
    const float* __restrict__ Jm, const float* __restrict__ W1, const float* __restrict__ b1v,
    const float* __restrict__ W2, const float* __restrict__ b2v,
    const float* __restrict__ W3, const float* __restrict__ b3,
    const float* __restrict__ gWih, const float* __restrict__ gWhh,
    const float* __restrict__ gbih, const float* __restrict__ gbhh,
    const float* __restrict__ bvec, const int* __restrict__ node_var)
{
    extern __shared__ float sm[];
    float* sW    = sm;           // W1T (130x129) -> W2T -> GRU weights
    float* sXT   = sm + 16772;   // [130][36]
    float* l1T   = sm + 21452;   // [128][36]
    float* sAB   = sm + 26060;
    float* sEm   = sm + 26124;
    float* sNew  = sm + 26188;
    float* sPart = sm + 26252;
    int t = threadIdx.x;
    int mb = blockIdx.x * 32;
    for (int i = t; i < 16640; i += 256) { int c = i / 130, k = i - c*130; sW[k*129+c] = W1[i]; }
    for (int i = t; i < 2048; i += 256) {
        int n = i >> 6, k = i & 63;
        sXT[k*36 + n]        = g_hv[(mb+n)*SD + k];
        sXT[(64+k)*36 + n]   = g_hf[(mb + (n^1))*SD + k];
    }
    if (t < 32) {
        int u = node_var[mb + t], vv = node_var[mb + (t^1)];
        sXT[128*36 + t] = bvec[u];
        sXT[129*36 + t] = bvec[vv];
        sAB[t*2]   = Jm[u*NV + vv];
        sAB[t*2+1] = Jm[vv*NV + u];
    }
    __syncthreads();
    int col = t & 127, e0 = (t >> 7)*4, wid = t >> 5, lane = t & 31;
    float rb1 = b1v[col], rb2 = b2v[col], w30 = W3[col], w31 = W3[HD+col];
    // layer1 for all 32 nodes
    #pragma unroll
    for (int g = 0; g < 4; g++) {
        int nb = g*8 + e0;
        float a0 = rb1, a1 = rb1, a2 = rb1, a3 = rb1;
        #pragma unroll 2
        for (int k = 0; k < 130; k++) {
            float ww = sW[k*129 + col];
            float4 X = *(const float4*)&sXT[k*36 + nb];
            a0 = fmaf(X.x, ww, a0); a1 = fmaf(X.y, ww, a1);
            a2 = fmaf(X.z, ww, a2); a3 = fmaf(X.w, ww, a3);
        }
        *(float4*)&l1T[col*36 + nb] =
            make_float4(fmaxf(a0,0.f), fmaxf(a1,0.f), fmaxf(a2,0.f), fmaxf(a3,0.f));
    }
    __syncthreads();
    for (int i = t; i < 16384; i += 256) { int c = i >> 7, k = i & 127; sW[k*129+c] = W2[i]; }
    __syncthreads();
    // layer2 + layer3
    for (int g = 0; g < 4; g++) {
        int nb = g*8 + e0;
        float a0 = rb2, a1 = rb2, a2 = rb2, a3 = rb2;
        #pragma unroll 8
        for (int k = 0; k < 128; k++) {
            float ww = sW[k*129 + col];
            float4 L = *(const float4*)&l1T[k*36 + nb];
            a0 = fmaf(L.x, ww, a0); a1 = fmaf(L.y, ww, a1);
            a2 = fmaf(L.z, ww, a2); a3 = fmaf(L.w, ww, a3);
        }
        float av[4] = {a0, a1, a2, a3};
        #pragma unroll
        for (int q = 0; q < 4; q++) {
            float l2 = fmaxf(av[q], 0.f);
            float p0 = l2*w30, p1 = l2*w31;
            #pragma unroll
            for (int off = 16; off; off >>= 1) {
                p0 += __shfl_xor_sync(0xffffffffu, p0, off);
                p1 += __shfl_xor_sync(0xffffffffu, p1, off);
            }
            if (lane == 0) { sPart[(wid*4+q)*2] = p0; sPart[(wid*4+q)*2+1] = p1; }
        }
        __syncthreads();
        if (t < 16) {
            int el = t >> 1, c = t & 1;
            int q = el & 3, hw = (el >> 2) * 4;
            float s = sPart[((hw+0)*4+q)*2+c] + sPart[((hw+1)*4+q)*2+c]
                    + sPart[((hw+2)*4+q)*2+c] + sPart[((hw+3)*4+q)*2+c];
            sEm[(g*8 + el)*2 + c] = s + b3[c];
        }
        __syncthreads();
    }
    // per-node logsumexp over 2x2 factor table
    if (t < 64) {
        int n = t >> 1, c = t & 1;
        float A = sAB[n*2], B = sAB[n*2+1];
        float em0 = sEm[n*2], em1 = sEm[n*2+1];
        float a = (c == 0) ? (A + B + em0) : (-2.f*A + em0);
        float d = (c == 0) ? (-2.f*B + em1) : (A + B + em1);
        float mx = fmaxf(a, d), mn = fminf(a, d);
        sNew[n*2 + c] = mx + log1pf(expf(mn - mx));
    }
    __syncthreads();
    // GRU(h_f2v), x = new[sib]
    float* sWih = sW + 12480; float* sbih = sW + 12864; float* sbhh = sW + 13056;
    for (int i = t; i < 12288; i += 256) { int q = i >> 6, k = i & 63; sW[q*65+k] = gWhh[i]; }
    for (int i = t; i < 384; i += 256) sWih[i] = gWih[i];
    if (t < 192) { sbih[t] = gbih[t]; sbhh[t] = gbhh[t]; }
    __syncthreads();
    int nn = t >> 3, s0b = t & 7, sibl = nn ^ 1;
    float x0 = sNew[sibl*2], x1 = sNew[sibl*2 + 1];
    #pragma unroll
    for (int j2 = 0; j2 < 8; j2++) {
        int s = s0b + j2*8;
        float gir = fmaf(x1, sWih[2*s+1],       fmaf(x0, sWih[2*s],       sbih[s]));
        float giz = fmaf(x1, sWih[2*(64+s)+1],  fmaf(x0, sWih[2*(64+s)],  sbih[64+s]));
        float gin = fmaf(x1, sWih[2*(128+s)+1], fmaf(x0, sWih[2*(128+s)], sbih[128+s]));
        float ghr = sbhh[s], ghz = sbhh[64+s], ghn = sbhh[128+s];
        const float* wr = sW + s*65;
        const float* wz = sW + (64+s)*65;
        const float* wg = sW + (128+s)*65;
        #pragma unroll 8
        for (int k = 0; k < 64; k++) {
            float h = sXT[(64+k)*36 + sibl];   // == h_f2v[mb+nn][k]
            ghr = fmaf(h, wr[k], ghr);
            ghz = fmaf(h, wz[k], ghz);
            ghn = fmaf(h, wg[k], ghn);
        }
        float r  = sigm(gir + ghr);
        float z  = sigm(giz + ghz);
        float gg = tanh_fast(fmaf(r, ghn, gin));
        float h  = sXT[(64+s)*36 + sibl];
        g_hf[(mb+nn)*SD + s] = fmaf(z, h - gg, gg);
    }
}

// ---------------- K4: readout MLP + softmax ----------------
// smem floats: sW1 8256 | sW2 16512 | snm 64 | sh1 128 | sh2 128 | sp 8 = 25096
#define K4_SMEM (25096*4)
__global__ void __launch_bounds__(128) k4_readout(
    const float* __restrict__ W1, const float* __restrict__ b1,
    const float* __restrict__ W2, const float* __restrict__ b2,
    const float* __restrict__ W3, const float* __restrict__ b3,
    float* __restrict__ out)
{
    extern __shared__ float sm[];
    float* sW1 = sm;
    float* sW2 = sm + 8256;
    float* snm = sm + 24768;
    float* sh1 = sm + 24832;
    float* sh2 = sm + 24960;
    float* sp  = sm + 25088;
    int t = threadIdx.x, v = blockIdx.x;
    for (int i = t; i < 8192; i += 128)  { int c = i >> 6, k = i & 63;  sW1[k*129+c] = W1[i]; }
    for (int i = t; i < 16384; i += 128) { int c = i >> 7, k = i & 127; sW2[k*129+c] = W2[i]; }
    if (t < 64) {
        float s = 0.f;
        #pragma unroll
        for (int d = 0; d < 8; d++) s += g_hf[g_varlist[v*DEG + d]*SD + t];
        snm[t] = s;
    }
    __syncthreads();
    {
        float acc = b1[t];
        #pragma unroll 8
        for (int k = 0; k < 64; k++) acc = fmaf(snm[k], sW1[k*129 + t], acc);
        sh1[t] = fmaxf(acc, 0.f);
    }
    __syncthreads();
    {
        float acc = b2[t];
        #pragma unroll 8
        for (int k = 0; k < 128; k++) acc = fmaf(sh1[k], sW2[k*129 + t], acc);
        sh2[t] = fmaxf(acc, 0.f);
    }
    __syncthreads();
    float h2 = sh2[t];
    float p0 = h2 * W3[t], p1 = h2 * W3[128 + t];
    #pragma unroll
    for (int off = 16; off; off >>= 1) {
        p0 += __shfl_xor_sync(0xffffffffu, p0, off);
        p1 += __shfl_xor_sync(0xffffffffu, p1, off);
    }
    int wid = t >> 5;
    if ((t & 31) == 0) { sp[wid*2] = p0; sp[wid*2+1] = p1; }
    __syncthreads();
    if (t == 0) {
        float l0 = sp[0] + sp[2] + sp[4] + sp[6] + b3[0];
        float l1 = sp[1] + sp[3] + sp[5] + sp[7] + b3[1];
        float m = fmaxf(l0, l1);
        float e0 = expf(l0 - m), e1 = expf(l1 - m);
        float inv = 1.f / (e0 + e1);
        out[v*2]     = e0 * inv;
        out[v*2 + 1] = e1 * inv;
    }
}

// ---------------- launch ----------------
extern "C" void kernel_launch(void* const* d_in, const int* in_sizes, int n_in,
                              void* d_out, int out_size) {
    (void)in_sizes; (void)n_in; (void)out_size;
    const float* J        = (const float*)d_in[0];
    const float* b        = (const float*)d_in[1];
    const int*   node_var = (const int*)  d_in[2];
    // d_in[3], d_in[4] (e1_row, e1_col) intentionally unused (structure rebuilt on device)
    const float* v2f_W1 = (const float*)d_in[5];
    const float* v2f_b1 = (const float*)d_in[6];
    const float* v2f_W2 = (const float*)d_in[7];
    const float* v2f_b2 = (const float*)d_in[8];
    const float* v2f_W3 = (const float*)d_in[9];
    const float* v2f_b3 = (const float*)d_in[10];
    const float* f2v_W1 = (const float*)d_in[11];
    const float* f2v_b1 = (const float*)d_in[12];
    const float* f2v_W2 = (const float*)d_in[13];
    const float* f2v_b2 = (const float*)d_in[14];
    const float* f2v_W3 = (const float*)d_in[15];
    const float* f2v_b3 = (const float*)d_in[16];
    const float* gv_Wih = (const float*)d_in[17];
    const float* gv_Whh = (const float*)d_in[18];
    const float* gv_bih = (const float*)d_in[19];
    const float* gv_bhh = (const float*)d_in[20];
    const float* gf_Wih = (const float*)d_in[21];
    const float* gf_Whh = (const float*)d_in[22];
    const float* gf_bih = (const float*)d_in[23];
    const float* gf_bhh = (const float*)d_in[24];
    const float* ro_W1  = (const float*)d_in[25];
    const float* ro_b1  = (const float*)d_in[26];
    const float* ro_W2  = (const float*)d_in[27];
    const float* ro_b2  = (const float*)d_in[28];
    const float* ro_W3  = (const float*)d_in[29];
    const float* ro_b3  = (const float*)d_in[30];

    cudaFuncSetAttribute((const void*)k1_pq,      cudaFuncAttributeMaxDynamicSharedMemorySize, K1_SMEM);
    cudaFuncSetAttribute((const void*)k2_edges,   cudaFuncAttributeMaxDynamicSharedMemorySize, K2_SMEM);
    cudaFuncSetAttribute((const void*)k3_f2v,     cudaFuncAttributeMaxDynamicSharedMemorySize, K3_SMEM);
    cudaFuncSetAttribute((const void*)k4_readout, cudaFuncAttributeMaxDynamicSharedMemorySize, K4_SMEM);

    k_init_a<<<2048, 256>>>();
    k_init_b<<<32, 256>>>(node_var);
    k_init_c<<<4, 256>>>();
    for (int s = 0; s < NSTEPS; s++) {
        k1_pq<<<NM/64, 256, K1_SMEM>>>(v2f_W1, v2f_b1, b, node_var);
        k2_edges<<<NV, 256, K2_SMEM>>>(v2f_W2, v2f_b2, v2f_W3, v2f_b3,
                                       gv_Wih, gv_Whh, gv_bih, gv_bhh);
        k3_f2v<<<NM/32, 256, K3_SMEM>>>(J, f2v_W1, f2v_b1, f2v_W2, f2v_b2, f2v_W3, f2v_b3,
                                        gf_Wih, gf_Whh, gf_bih, gf_bhh, b, node_var);
    }
    k4_readout<<<NV, 128, K4_SMEM>>>(ro_W1, ro_b1, ro_W2, ro_b2, ro_W3, ro_b3, (float*)d_out);
}

// round 9
// speedup vs baseline: 1.1100x; 1.1100x over previous
#include <cuda_runtime.h>
#include <math.h>

#define NV 1024
#define NM 8192
#define DEG 8
#define SD 64
#define HD 128
#define NSTEPS 10

typedef unsigned long long u64;

__device__ __forceinline__ u64 pk2(float lo, float hi) {
    u64 r; asm("mov.b64 %0,{%1,%2};" : "=l"(r) : "f"(lo), "f"(hi)); return r;
}
__device__ __forceinline__ void up2(u64 v, float& lo, float& hi) {
    asm("mov.b64 {%0,%1},%2;" : "=f"(lo), "=f"(hi) : "l"(v));
}
__device__ __forceinline__ void fma2(u64& d, u64 a, u64 b) {
    asm("fma.rn.f32x2 %0,%1,%2,%0;" : "+l"(d) : "l"(a), "l"(b));
}

// ---------------- persistent device state ----------------
__device__ float g_hv[NM*SD];     // h_v2f
__device__ float g_hf[NM*SD];     // h_f2v
__device__ float g_P [NM*HD];
__device__ float g_Q [NM*HD];
__device__ int   g_varlist[NV*DEG];
__device__ int   g_cnt[NV];

__device__ __forceinline__ float sigm(float x) {
    return __fdividef(1.f, 1.f + __expf(-x));
}
__device__ __forceinline__ float tanh_fast(float x) {
    return 1.f - __fdividef(2.f, __expf(2.f*x) + 1.f);
}

// ---------------- init ----------------
__global__ void k_init_a() {
    int idx = blockIdx.x*blockDim.x + threadIdx.x;
    if (idx < NV) g_cnt[idx] = 0;
    if (idx < NM*SD) { g_hv[idx] = 0.f; g_hf[idx] = 0.f; }
}
__global__ void k_init_b(const int* __restrict__ node_var) {
    int m = blockIdx.x*blockDim.x + threadIdx.x;
    if (m >= NM) return;
    int u = node_var[m];
    int pos = atomicAdd(&g_cnt[u], 1);
    g_varlist[u*DEG + pos] = m;
}
__global__ void k_init_c() {
    int v = blockIdx.x*blockDim.x + threadIdx.x;
    if (v >= NV) return;
    int* p = &g_varlist[v*DEG];
    for (int a = 1; a < DEG; a++) {
        int key = p[a]; int b = a - 1;
        while (b >= 0 && p[b] > key) { p[b+1] = p[b]; b--; }
        p[b+1] = key;
    }
}

// ---------------- K1: P/Q precompute (16 nodes/block, 512 blocks) --------
// smem floats: sW1 16512 | shf 64*16 | shv 64*16 | sbv 16 = 18576 (74.3KB, 3 CTA/SM)
#define K1_SMEM (18576*4)
__global__ void __launch_bounds__(256) k1_pq(
    const float* __restrict__ W1, const float* __restrict__ b1,
    const float* __restrict__ bvec, const int* __restrict__ node_var)
{
    extern __shared__ float sm[];
    float* sW1 = sm;
    float* shf = sm + 16512;
    float* shv = sm + 17536;
    float* sbv = sm + 18560;
    int t = threadIdx.x;
    int mb = blockIdx.x * 16;
    const float4* W14 = (const float4*)W1;
    float4* sW14 = (float4*)sW1;
    for (int i = t; i < 4128; i += 256) sW14[i] = W14[i];
    for (int i = t; i < 1024; i += 256) {
        int n = i >> 6, k = i & 63;
        shf[k*16+n] = g_hf[(mb+n)*SD + k];
        shv[k*16+n] = g_hv[(mb+n)*SD + k];
    }
    if (t < 16) sbv[t] = bvec[node_var[mb+t]];
    __syncthreads();
    int col = t & 127, part = t >> 7;
    float rb1 = b1[col];
    float wlast = sW1[col*129 + 128];
    const float* hT = part ? shv : shf;
    const float* wrow = sW1 + col*129 + (part ? 64 : 0);
    float* dst = part ? g_Q : g_P;
    u64 acc[8];
    #pragma unroll
    for (int p = 0; p < 8; p++) {
        if (part) acc[p] = pk2(fmaf(sbv[2*p], wlast, rb1), fmaf(sbv[2*p+1], wlast, rb1));
        else acc[p] = 0ULL;
    }
    #pragma unroll 4
    for (int k = 0; k < 64; k++) {
        float w = wrow[k];
        u64 w2 = pk2(w, w);
        const u64* hp = (const u64*)&hT[k*16];
        #pragma unroll
        for (int p = 0; p < 8; p++) fma2(acc[p], hp[p], w2);
    }
    #pragma unroll
    for (int p = 0; p < 8; p++) {
        float f0, f1; up2(acc[p], f0, f1);
        dst[(mb+2*p)*HD + col]   = f0;
        dst[(mb+2*p+1)*HD + col] = f1;
    }
}

// ---------------- K2: per-variable edge MLP + segsum + GRU(h_v2f) -------
// smem floats: sW2T 16512 | sP 1024 | sQ 1024 | l1T 128*56 | sPart 448 | snm 16 = 26192
#define K2_SMEM (26192*4)
__global__ void __launch_bounds__(256) k2_edges(
    const float* __restrict__ W2, const float* __restrict__ b2v,
    const float* __restrict__ W3, const float* __restrict__ b3,
    const float* __restrict__ gWih, const float* __restrict__ gWhh,
    const float* __restrict__ gbih, const float* __restrict__ gbhh)
{
    extern __shared__ float sm[];
    __shared__ int smIdx[8];
    float* sW2T  = sm;
    float* sP    = sm + 16512;
    float* sQ    = sm + 17536;
    float* l1T   = sm + 18560;   // [128][56]
    float* sPart = sm + 25728;   // [7][32][2]
    float* snm   = sm + 26176;   // [8][2]
    int t = threadIdx.x, v = blockIdx.x;
    if (t < 8) smIdx[t] = g_varlist[v*DEG + t];
    // W2 transposed load, vectorized
    for (int i4 = t; i4 < 4096; i4 += 256) {
        float4 w = ((const float4*)W2)[i4];
        int base = i4 * 4;
        int cc = base >> 7, k = base & 127;
        sW2T[(k+0)*129 + cc] = w.x;
        sW2T[(k+1)*129 + cc] = w.y;
        sW2T[(k+2)*129 + cc] = w.z;
        sW2T[(k+3)*129 + cc] = w.w;
    }
    __syncthreads();   // smIdx visible
    for (int i = t; i < 256; i += 256) {
        int n = i >> 5, f = i & 31;
        ((float4*)sP)[i] = ((const float4*)(g_P + smIdx[n]*HD))[f];
        ((float4*)sQ)[i] = ((const float4*)(g_Q + smIdx[n]*HD))[f];
    }
    __syncthreads();
    int col = t & 127, half = t >> 7, e0 = half*4, wid = t >> 5, lane = t & 31;
    float rb2 = b2v[col], w30 = W3[col], w31 = W3[HD + col];
    // ---- stage all 56 edges' layer-1 (one pass, one sync)
    #pragma unroll
    for (int g = 0; g < 7; g++) {
        int be = g*8 + e0;
        float l1v[4];
        #pragma unroll
        for (int q = 0; q < 4; q++) {
            int e = be + q, ii = e/7, jj = e - ii*7;
            int j = jj + (jj >= ii);
            l1v[q] = fmaxf(sP[j*HD + col] + sQ[ii*HD + col], 0.f);
        }
        *(float4*)&l1T[col*56 + be] = make_float4(l1v[0], l1v[1], l1v[2], l1v[3]);
    }
    __syncthreads();
    // ---- layer2 + layer3, 7 chunks, no intermediate syncs
    #pragma unroll 1
    for (int g = 0; g < 7; g++) {
        int be = g*8 + e0;
        u64 acc01 = pk2(rb2, rb2), acc23 = acc01;
        #pragma unroll 8
        for (int k = 0; k < 128; k++) {
            float w = sW2T[k*129 + col];
            u64 w2 = pk2(w, w);
            ulonglong2 L = *(const ulonglong2*)&l1T[k*56 + be];
            fma2(acc01, L.x, w2);
            fma2(acc23, L.y, w2);
        }
        float a0, a1, a2, a3;
        up2(acc01, a0, a1); up2(acc23, a2, a3);
        float av[4] = {a0, a1, a2, a3};
        #pragma unroll
        for (int q = 0; q < 4; q++) {
            float l2 = fmaxf(av[q], 0.f);
            float p0 = l2*w30, p1 = l2*w31;
            #pragma unroll
            for (int off = 16; off; off >>= 1) {
                p0 += __shfl_xor_sync(0xffffffffu, p0, off);
                p1 += __shfl_xor_sync(0xffffffffu, p1, off);
            }
            if (lane == 0) { sPart[g*64 + (wid*4+q)*2] = p0; sPart[g*64 + (wid*4+q)*2 + 1] = p1; }
        }
    }
    __syncthreads();
    // ---- final deterministic segment-sum (t<16) overlapped with GRU weight loads
    if (t < 16) {
        int ii = t >> 1, c = t & 1;
        float s = 0.f;
        for (int jj = 0; jj < 7; jj++) {
            int e = ii*7 + jj;
            int g = e >> 3, slot = e & 7;
            int q = slot & 3, h4 = (slot >> 2) * 4;
            s += sPart[g*64 + ((h4+0)*4+q)*2 + c];
            s += sPart[g*64 + ((h4+1)*4+q)*2 + c];
            s += sPart[g*64 + ((h4+2)*4+q)*2 + c];
            s += sPart[g*64 + ((h4+3)*4+q)*2 + c];
        }
        snm[ii*2 + c] = s;
    }
    // GRU weights overlay sW2T (dead after layer2); sHv overlays sP (dead)
    float* sWhh = sm;            // [192][65]
    float* sWih = sm + 12480;    // 384
    float* sbih = sm + 12864;    // 192
    float* sbhh = sm + 13056;    // 192
    float* sHv  = sm + 16512;    // [8][65]
    for (int i4 = t; i4 < 3072; i4 += 256) {
        float4 w = ((const float4*)gWhh)[i4];
        int base = i4*4, q = base >> 6, k = base & 63;
        sWhh[q*65 + k + 0] = w.x;
        sWhh[q*65 + k + 1] = w.y;
        sWhh[q*65 + k + 2] = w.z;
        sWhh[q*65 + k + 3] = w.w;
    }
    for (int i4 = t; i4 < 96; i4 += 256) ((float4*)sWih)[i4] = ((const float4*)gWih)[i4];
    if (t < 192) { sbih[t] = gbih[t]; sbhh[t] = gbhh[t]; }
    for (int i4 = t; i4 < 128; i4 += 256) {
        int n = i4 >> 4, r = (i4 & 15) * 4;
        float4 h = ((const float4*)(g_hv + smIdx[n]*SD))[i4 & 15];
        sHv[n*65 + r + 0] = h.x;
        sHv[n*65 + r + 1] = h.y;
        sHv[n*65 + r + 2] = h.z;
        sHv[n*65 + r + 3] = h.w;
    }
    __syncthreads();
    float sb30 = 7.f*b3[0], sb31 = 7.f*b3[1];
    int nn = t >> 5, s0 = t & 31;
    float x0 = snm[nn*2] + sb30, x1 = snm[nn*2+1] + sb31;
    const float* hrow = sHv + nn*65;
    #pragma unroll
    for (int j2 = 0; j2 < 2; j2++) {
        int s = s0 + j2*32;
        float gir = fmaf(x1, sWih[2*s+1],       fmaf(x0, sWih[2*s],       sbih[s]));
        float giz = fmaf(x1, sWih[2*(64+s)+1],  fmaf(x0, sWih[2*(64+s)],  sbih[64+s]));
        float gin = fmaf(x1, sWih[2*(128+s)+1], fmaf(x0, sWih[2*(128+s)], sbih[128+s]));
        float ghr = sbhh[s], ghz = sbhh[64+s], ghn = sbhh[128+s];
        const float* wr = sWhh + s*65;
        const float* wz = sWhh + (64+s)*65;
        const float* wg = sWhh + (128+s)*65;
        #pragma unroll 8
        for (int k = 0; k < 64; k++) {
            float h = hrow[k];
            ghr = fmaf(h, wr[k], ghr);
            ghz = fmaf(h, wz[k], ghz);
            ghn = fmaf(h, wg[k], ghn);
        }
        float r  = sigm(gir + ghr);
        float z  = sigm(giz + ghz);
        float gg = tanh_fast(fmaf(r, ghn, gin));
        float h  = hrow[s];
        g_hv[smIdx[nn]*SD + s] = fmaf(z, h - gg, gg);
    }
}

// ---------------- K3: f2v MLP + logsumexp + GRU(h_f2v) ----------------
// smem floats: sW 16772 | sXT 130*36 | l1T 128*36 | sAB 64 | sEm 64 | sNew 64 | sPart 64 = 26316
#define K3_SMEM (26316*4)
__global__ void __launch_bounds__(256) k3_f2v(
    const float* __restrict__ Jm, const float* __restrict__ W1, const float* __restrict__ b1v,
    const float* __restrict__ W2, const float* __restrict__ b2v,
    const float* __restrict__ W3, const float* __restrict__ b3,
    const float* __restrict__ gWih, const float* __restrict__ gWhh,
    const float* __restrict__ gbih, const float* __restrict__ gbhh,
    const float* __restrict__ bvec, const int* __restrict__ node_var)
{
    extern __shared__ float sm[];
    float* sW    = sm;           // W1T (130x129) -> W2T -> GRU weights
    float* sXT   = sm + 16772;   // [130][36]
    float* l1T   = sm + 21452;   // [128][36]
    float* sAB   = sm + 26060;
    float* sEm   = sm + 26124;
    float* sNew  = sm + 26188;
    float* sPart = sm + 26252;
    int t = threadIdx.x;
    int mb = blockIdx.x * 32;
    for (int i4 = t; i4 < 4160; i4 += 256) {
        float4 w = ((const float4*)W1)[i4];
        int base = i4 * 4;
        #pragma unroll
        for (int j = 0; j < 4; j++) {
            int i = base + j;
            int cc = i / 130, k = i - cc*130;
            sW[k*129 + cc] = ((const float*)&w)[j];
        }
    }
    for (int i = t; i < 2048; i += 256) {
        int n = i >> 6, k = i & 63;
        sXT[k*36 + n]        = g_hv[(mb+n)*SD + k];
        sXT[(64+k)*36 + n]   = g_hf[(mb + (n^1))*SD + k];
    }
    if (t < 32) {
        int u = node_var[mb + t], vv = node_var[mb + (t^1)];
        sXT[128*36 + t] = bvec[u];
        sXT[129*36 + t] = bvec[vv];
        sAB[t*2]   = Jm[u*NV + vv];
        sAB[t*2+1] = Jm[vv*NV + u];
    }
    __syncthreads();
    int col = t & 127, e0 = (t >> 7)*4, wid = t >> 5, lane = t & 31;
    float rb1 = b1v[col], rb2 = b2v[col], w30 = W3[col], w31 = W3[HD+col];
    // layer1 for all 32 nodes (f32x2)
    #pragma unroll
    for (int g = 0; g < 4; g++) {
        int nb = g*8 + e0;
        u64 a01 = pk2(rb1, rb1), a23 = a01;
        #pragma unroll 2
        for (int k = 0; k < 130; k++) {
            float w = sW[k*129 + col];
            u64 w2 = pk2(w, w);
            ulonglong2 X = *(const ulonglong2*)&sXT[k*36 + nb];
            fma2(a01, X.x, w2);
            fma2(a23, X.y, w2);
        }
        float a0, a1, a2, a3;
        up2(a01, a0, a1); up2(a23, a2, a3);
        *(float4*)&l1T[col*36 + nb] =
            make_float4(fmaxf(a0,0.f), fmaxf(a1,0.f), fmaxf(a2,0.f), fmaxf(a3,0.f));
    }
    __syncthreads();
    for (int i4 = t; i4 < 4096; i4 += 256) {
        float4 w = ((const float4*)W2)[i4];
        int base = i4*4, cc = base >> 7, k = base & 127;
        sW[(k+0)*129 + cc] = w.x;
        sW[(k+1)*129 + cc] = w.y;
        sW[(k+2)*129 + cc] = w.z;
        sW[(k+3)*129 + cc] = w.w;
    }
    __syncthreads();
    // layer2 + layer3
    #pragma unroll 1
    for (int g = 0; g < 4; g++) {
        int nb = g*8 + e0;
        u64 a01 = pk2(rb2, rb2), a23 = a01;
        #pragma unroll 8
        for (int k = 0; k < 128; k++) {
            float w = sW[k*129 + col];
            u64 w2 = pk2(w, w);
            ulonglong2 L = *(const ulonglong2*)&l1T[k*36 + nb];
            fma2(a01, L.x, w2);
            fma2(a23, L.y, w2);
        }
        float a0, a1, a2, a3;
        up2(a01, a0, a1); up2(a23, a2, a3);
        float av[4] = {a0, a1, a2, a3};
        #pragma unroll
        for (int q = 0; q < 4; q++) {
            float l2 = fmaxf(av[q], 0.f);
            float p0 = l2*w30, p1 = l2*w31;
            #pragma unroll
            for (int off = 16; off; off >>= 1) {
                p0 += __shfl_xor_sync(0xffffffffu, p0, off);
                p1 += __shfl_xor_sync(0xffffffffu, p1, off);
            }
            if (lane == 0) { sPart[(wid*4+q)*2] = p0; sPart[(wid*4+q)*2+1] = p1; }
        }
        __syncthreads();
        if (t < 16) {
            int el = t >> 1, c = t & 1;
            int q = el & 3, hw = (el >> 2) * 4;
            float s = sPart[((hw+0)*4+q)*2+c] + sPart[((hw+1)*4+q)*2+c]
                    + sPart[((hw+2)*4+q)*2+c] + sPart[((hw+3)*4+q)*2+c];
            sEm[(g*8 + el)*2 + c] = s + b3[c];
        }
        __syncthreads();
    }
    // per-node logsumexp over 2x2 factor table
    if (t < 64) {
        int n = t >> 1, c = t & 1;
        float A = sAB[n*2], B = sAB[n*2+1];
        float em0 = sEm[n*2], em1 = sEm[n*2+1];
        float a = (c == 0) ? (A + B + em0) : (-2.f*A + em0);
        float d = (c == 0) ? (-2.f*B + em1) : (A + B + em1);
        float mx = fmaxf(a, d), mn = fminf(a, d);
        sNew[n*2 + c] = mx + log1pf(expf(mn - mx));
    }
    __syncthreads();
    // GRU(h_f2v), x = new[sib]; weights overlay sW
    float* sWih = sW + 12480; float* sbih = sW + 12864; float* sbhh = sW + 13056;
    for (int i4 = t; i4 < 3072; i4 += 256) {
        float4 w = ((const float4*)gWhh)[i4];
        int base = i4*4, q = base >> 6, k = base & 63;
        sW[q*65 + k + 0] = w.x;
        sW[q*65 + k + 1] = w.y;
        sW[q*65 + k + 2] = w.z;
        sW[q*65 + k + 3] = w.w;
    }
    for (int i4 = t; i4 < 96; i4 += 256) ((float4*)sWih)[i4] = ((const float4*)gWih)[i4];
    if (t < 192) { sbih[t] = gbih[t]; sbhh[t] = gbhh[t]; }
    __syncthreads();
    int nn = t >> 3, s0b = t & 7, sibl = nn ^ 1;
    float x0 = sNew[sibl*2], x1 = sNew[sibl*2 + 1];
    #pragma unroll
    for (int j2 = 0; j2 < 8; j2++) {
        int s = s0b + j2*8;
        float gir = fmaf(x1, sWih[2*s+1],       fmaf(x0, sWih[2*s],       sbih[s]));
        float giz = fmaf(x1, sWih[2*(64+s)+1],  fmaf(x0, sWih[2*(64+s)],  sbih[64+s]));
        float gin = fmaf(x1, sWih[2*(128+s)+1], fmaf(x0, sWih[2*(128+s)], sbih[128+s]));
        float ghr = sbhh[s], ghz = sbhh[64+s], ghn = sbhh[128+s];
        const float* wr = sW + s*65;
        const float* wz = sW + (64+s)*65;
        const float* wg = sW + (128+s)*65;
        #pragma unroll 8
        for (int k = 0; k < 64; k++) {
            float h = sXT[(64+k)*36 + sibl];   // == h_f2v[mb+nn][k]
            ghr = fmaf(h, wr[k], ghr);
            ghz = fmaf(h, wz[k], ghz);
            ghn = fmaf(h, wg[k], ghn);
        }
        float r  = sigm(gir + ghr);
        float z  = sigm(giz + ghz);
        float gg = tanh_fast(fmaf(r, ghn, gin));
        float h  = sXT[(64+s)*36 + sibl];
        g_hf[(mb+nn)*SD + s] = fmaf(z, h - gg, gg);
    }
}

// ---------------- K4: readout MLP + softmax ----------------
// smem floats: sW1 8256 | sW2 16512 | snm 64 | sh1 128 | sh2 128 | sp 8 = 25096
#define K4_SMEM (25096*4)
__global__ void __launch_bounds__(128) k4_readout(
    const float* __restrict__ W1, const float* __restrict__ b1,
    const float* __restrict__ W2, const float* __restrict__ b2,
    const float* __restrict__ W3, const float* __restrict__ b3,
    float* __restrict__ out)
{
    extern __shared__ float sm[];
    float* sW1 = sm;
    float* sW2 = sm + 8256;
    float* snm = sm + 24768;
    float* sh1 = sm + 24832;
    float* sh2 = sm + 24960;
    float* sp  = sm + 25088;
    int t = threadIdx.x, v = blockIdx.x;
    for (int i = t; i < 8192; i += 128)  { int c = i >> 6, k = i & 63;  sW1[k*129+c] = W1[i]; }
    for (int i = t; i < 16384; i += 128) { int c = i >> 7, k = i & 127; sW2[k*129+c] = W2[i]; }
    if (t < 64) {
        float s = 0.f;
        #pragma unroll
        for (int d = 0; d < 8; d++) s += g_hf[g_varlist[v*DEG + d]*SD + t];
        snm[t] = s;
    }
    __syncthreads();
    {
        float acc = b1[t];
        #pragma unroll 8
        for (int k = 0; k < 64; k++) acc = fmaf(snm[k], sW1[k*129 + t], acc);
        sh1[t] = fmaxf(acc, 0.f);
    }
    __syncthreads();
    {
        float acc = b2[t];
        #pragma unroll 8
        for (int k = 0; k < 128; k++) acc = fmaf(sh1[k], sW2[k*129 + t], acc);
        sh2[t] = fmaxf(acc, 0.f);
    }
    __syncthreads();
    float h2 = sh2[t];
    float p0 = h2 * W3[t], p1 = h2 * W3[128 + t];
    #pragma unroll
    for (int off = 16; off; off >>= 1) {
        p0 += __shfl_xor_sync(0xffffffffu, p0, off);
        p1 += __shfl_xor_sync(0xffffffffu, p1, off);
    }
    int wid = t >> 5;
    if ((t & 31) == 0) { sp[wid*2] = p0; sp[wid*2+1] = p1; }
    __syncthreads();
    if (t == 0) {
        float l0 = sp[0] + sp[2] + sp[4] + sp[6] + b3[0];
        float l1 = sp[1] + sp[3] + sp[5] + sp[7] + b3[1];
        float m = fmaxf(l0, l1);
        float e0 = expf(l0 - m), e1 = expf(l1 - m);
        float inv = 1.f / (e0 + e1);
        out[v*2]     = e0 * inv;
        out[v*2 + 1] = e1 * inv;
    }
}

// ---------------- launch ----------------
extern "C" void kernel_launch(void* const* d_in, const int* in_sizes, int n_in,
                              void* d_out, int out_size) {
    (void)in_sizes; (void)n_in; (void)out_size;
    const float* J        = (const float*)d_in[0];
    const float* b        = (const float*)d_in[1];
    const int*   node_var = (const int*)  d_in[2];
    // d_in[3], d_in[4] (e1_row, e1_col) intentionally unused (structure rebuilt on device)
    const float* v2f_W1 = (const float*)d_in[5];
    const float* v2f_b1 = (const float*)d_in[6];
    const float* v2f_W2 = (const float*)d_in[7];
    const float* v2f_b2 = (const float*)d_in[8];
    const float* v2f_W3 = (const float*)d_in[9];
    const float* v2f_b3 = (const float*)d_in[10];
    const float* f2v_W1 = (const float*)d_in[11];
    const float* f2v_b1 = (const float*)d_in[12];
    const float* f2v_W2 = (const float*)d_in[13];
    const float* f2v_b2 = (const float*)d_in[14];
    const float* f2v_W3 = (const float*)d_in[15];
    const float* f2v_b3 = (const float*)d_in[16];
    const float* gv_Wih = (const float*)d_in[17];
    const float* gv_Whh = (const float*)d_in[18];
    const float* gv_bih = (const float*)d_in[19];
    const float* gv_bhh = (const float*)d_in[20];
    const float* gf_Wih = (const float*)d_in[21];
    const float* gf_Whh = (const float*)d_in[22];
    const float* gf_bih = (const float*)d_in[23];
    const float* gf_bhh = (const float*)d_in[24];
    const float* ro_W1  = (const float*)d_in[25];
    const float* ro_b1  = (const float*)d_in[26];
    const float* ro_W2  = (const float*)d_in[27];
    const float* ro_b2  = (const float*)d_in[28];
    const float* ro_W3  = (const float*)d_in[29];
    const float* ro_b3  = (const float*)d_in[30];

    cudaFuncSetAttribute((const void*)k1_pq,      cudaFuncAttributeMaxDynamicSharedMemorySize, K1_SMEM);
    cudaFuncSetAttribute((const void*)k2_edges,   cudaFuncAttributeMaxDynamicSharedMemorySize, K2_SMEM);
    cudaFuncSetAttribute((const void*)k3_f2v,     cudaFuncAttributeMaxDynamicSharedMemorySize, K3_SMEM);
    cudaFuncSetAttribute((const void*)k4_readout, cudaFuncAttributeMaxDynamicSharedMemorySize, K4_SMEM);

    k_init_a<<<2048, 256>>>();
    k_init_b<<<32, 256>>>(node_var);
    k_init_c<<<4, 256>>>();
    for (int s = 0; s < NSTEPS; s++) {
        k1_pq<<<NM/16, 256, K1_SMEM>>>(v2f_W1, v2f_b1, b, node_var);
        k2_edges<<<NV, 256, K2_SMEM>>>(v2f_W2, v2f_b2, v2f_W3, v2f_b3,
                                       gv_Wih, gv_Whh, gv_bih, gv_bhh);
        k3_f2v<<<NM/32, 256, K3_SMEM>>>(J, f2v_W1, f2v_b1, f2v_W2, f2v_b2, f2v_W3, f2v_b3,
                                        gf_Wih, gf_Whh, gf_bih, gf_bhh, b, node_var);
    }
    k4_readout<<<NV, 128, K4_SMEM>>>(ro_W1, ro_b1, ro_W2, ro_b2, ro_W3, ro_b3, (float*)d_out);
}

// round 10
// speedup vs baseline: 1.4441x; 1.3010x over previous
#include <cuda_runtime.h>
#include <math.h>

#define NV 1024
#define NM 8192
#define DEG 8
#define SD 64
#define HD 128
#define NSTEPS 10

typedef unsigned long long u64;

__device__ __forceinline__ u64 pk2(float lo, float hi) {
    u64 r; asm("mov.b64 %0,{%1,%2};" : "=l"(r) : "f"(lo), "f"(hi)); return r;
}
__device__ __forceinline__ void up2(u64 v, float& lo, float& hi) {
    asm("mov.b64 {%0,%1},%2;" : "=f"(lo), "=f"(hi) : "l"(v));
}
__device__ __forceinline__ void fma2(u64& d, u64 a, u64 b) {
    asm("fma.rn.f32x2 %0,%1,%2,%0;" : "+l"(d) : "l"(a), "l"(b));
}

// ---------------- persistent device state ----------------
__device__ float g_hv[NM*SD];     // h_v2f
__device__ float g_hf[NM*SD];     // h_f2v
__device__ float g_P [NM*HD];
__device__ float g_Q [NM*HD];
__device__ int   g_varlist[NV*DEG];
__device__ int   g_cnt[NV];

__device__ __forceinline__ float sigm(float x) {
    return __fdividef(1.f, 1.f + __expf(-x));
}
__device__ __forceinline__ float tanh_fast(float x) {
    return 1.f - __fdividef(2.f, __expf(2.f*x) + 1.f);
}

// ---------------- init ----------------
__global__ void k_init_a() {
    int idx = blockIdx.x*blockDim.x + threadIdx.x;
    if (idx < NV) g_cnt[idx] = 0;
    if (idx < NM*SD) { g_hv[idx] = 0.f; g_hf[idx] = 0.f; }
}
__global__ void k_init_b(const int* __restrict__ node_var) {
    int m = blockIdx.x*blockDim.x + threadIdx.x;
    if (m >= NM) return;
    int u = node_var[m];
    int pos = atomicAdd(&g_cnt[u], 1);
    g_varlist[u*DEG + pos] = m;
}
__global__ void k_init_c() {
    int v = blockIdx.x*blockDim.x + threadIdx.x;
    if (v >= NV) return;
    int* p = &g_varlist[v*DEG];
    for (int a = 1; a < DEG; a++) {
        int key = p[a]; int b = a - 1;
        while (b >= 0 && p[b] > key) { p[b+1] = p[b]; b--; }
        p[b+1] = key;
    }
}

// ---------------- K1: P/Q precompute, warp-broadcast tiling ----------------
// smem floats: sW1T 16768 (pitch 130, rows k=0..128) | shf 1024 | shv 1024 | sbv 16 = 18832
#define K1_SMEM (18832*4)
__global__ void __launch_bounds__(256, 3) k1_pq(
    const float* __restrict__ W1, const float* __restrict__ b1,
    const float* __restrict__ bvec, const int* __restrict__ node_var)
{
    extern __shared__ float sm[];
    float* sW1T = sm;            // [k 0..128][c 0..127] pitch 130
    float* shf  = sm + 16768;    // [k 0..63][n 0..15]
    float* shv  = sm + 17792;
    float* sbv  = sm + 18816;
    int t = threadIdx.x;
    int mb = blockIdx.x * 16;
    for (int i = t; i < 16512; i += 256) {
        int c = i / 129, k = i - c*129;
        sW1T[k*130 + c] = W1[i];
    }
    for (int i = t; i < 1024; i += 256) {
        int n = i >> 6, k = i & 63;
        shf[k*16+n] = g_hf[(mb+n)*SD + k];
        shv[k*16+n] = g_hv[(mb+n)*SD + k];
    }
    if (t < 16) sbv[t] = bvec[node_var[mb+t]];
    __syncthreads();
    int wid = t >> 5, lane = t & 31;
    #pragma unroll
    for (int iter = 0; iter < 2; iter++) {   // 0 = P (hf, W1a), 1 = Q (hv, W1b + bias)
        int nq = (wid & 3) * 4;              // node quad base
        int ch = wid >> 2;
        int c0 = ch*64 + lane*2;
        const float* hT = iter ? shv : shf;
        float* dst = iter ? g_Q : g_P;
        int kofs = iter ? 64 : 0;
        u64 acc[2][4];
        if (iter) {
            float wl0 = sW1T[128*130 + c0], wl1 = sW1T[128*130 + c0 + 1];
            float rb0 = b1[c0], rb1_ = b1[c0+1];
            #pragma unroll
            for (int np = 0; np < 4; np++) {
                float ba = sbv[nq + np];   // wait: packing is node pairs (2np,2np+1)? nq+np*? see below
                (void)ba;
            }
            #pragma unroll
            for (int np = 0; np < 2; np++) {
                // acc[c][p] packs nodes (nq+2p, nq+2p+1)
                float bA = sbv[nq + 2*np], bB = sbv[nq + 2*np + 1];
                acc[0][np] = pk2(fmaf(bA, wl0, rb0),  fmaf(bB, wl0, rb0));
                acc[1][np] = pk2(fmaf(bA, wl1, rb1_), fmaf(bB, wl1, rb1_));
            }
        } else {
            #pragma unroll
            for (int np = 0; np < 2; np++) { acc[0][np] = 0ULL; acc[1][np] = 0ULL; }
        }
        #pragma unroll 8
        for (int k = 0; k < 64; k++) {
            ulonglong2 h2 = *(const ulonglong2*)&hT[k*16 + nq];   // nodes nq..nq+3, broadcast
            u64 w01 = *(const u64*)&sW1T[(k + kofs)*130 + c0];
            float w0, w1; up2(w01, w0, w1);
            u64 w00 = pk2(w0, w0), w11 = pk2(w1, w1);
            fma2(acc[0][0], h2.x, w00);
            fma2(acc[0][1], h2.y, w00);
            fma2(acc[1][0], h2.x, w11);
            fma2(acc[1][1], h2.y, w11);
        }
        #pragma unroll
        for (int np = 0; np < 2; np++) {
            float a0A, a0B, a1A, a1B;
            up2(acc[0][np], a0A, a0B);
            up2(acc[1][np], a1A, a1B);
            int nA = mb + nq + 2*np, nB = nA + 1;
            *(float2*)&dst[nA*HD + c0] = make_float2(a0A, a1A);
            *(float2*)&dst[nB*HD + c0] = make_float2(a0B, a1B);
        }
    }
}

// ---------------- K2: per-variable edge MLP + segsum + GRU(h_v2f) -------
// smem floats: sW2T 16640 (pitch 130) | sP 1024 | sQ 1024 | l1T 7168 | sPart 256 | snm 16 = 26128
#define K2_SMEM (26128*4)
__global__ void __launch_bounds__(256) k2_edges(
    const float* __restrict__ W2, const float* __restrict__ b2v,
    const float* __restrict__ W3, const float* __restrict__ b3,
    const float* __restrict__ gWih, const float* __restrict__ gWhh,
    const float* __restrict__ gbih, const float* __restrict__ gbhh)
{
    extern __shared__ float sm[];
    __shared__ int smIdx[8];
    float* sW2T  = sm;           // [k][c] pitch 130
    float* sP    = sm + 16640;
    float* sQ    = sm + 17664;
    float* l1T   = sm + 18688;   // [col 0..127][edge 0..55] pitch 56
    float* sPart = sm + 25856;   // [g 0..6][ch 0..1][e 0..7][2]
    float* snm   = sm + 26112;   // [8][2]
    int t = threadIdx.x, v = blockIdx.x;
    if (t < 8) smIdx[t] = g_varlist[v*DEG + t];
    for (int i4 = t; i4 < 4096; i4 += 256) {
        float4 w = ((const float4*)W2)[i4];
        int base = i4 * 4;
        int cc = base >> 7, k = base & 127;
        sW2T[(k+0)*130 + cc] = w.x;
        sW2T[(k+1)*130 + cc] = w.y;
        sW2T[(k+2)*130 + cc] = w.z;
        sW2T[(k+3)*130 + cc] = w.w;
    }
    __syncthreads();   // smIdx visible
    for (int i = t; i < 256; i += 256) {
        int n = i >> 5, f = i & 31;
        ((float4*)sP)[i] = ((const float4*)(g_P + smIdx[n]*HD))[f];
        ((float4*)sQ)[i] = ((const float4*)(g_Q + smIdx[n]*HD))[f];
    }
    __syncthreads();
    // ---- stage all 56 edges' layer-1
    {
        int col = t & 127, e0 = (t >> 7) * 4;
        #pragma unroll
        for (int g = 0; g < 7; g++) {
            int be = g*8 + e0;
            float l1v[4];
            #pragma unroll
            for (int q = 0; q < 4; q++) {
                int e = be + q, ii = e/7, jj = e - ii*7;
                int j = jj + (jj >= ii);
                l1v[q] = fmaxf(sP[j*HD + col] + sQ[ii*HD + col], 0.f);
            }
            *(float4*)&l1T[col*56 + be] = make_float4(l1v[0], l1v[1], l1v[2], l1v[3]);
        }
    }
    __syncthreads();
    // ---- layer2+layer3: warp tasks (g, colhalf), 2 passes
    int wid = t >> 5, lane = t & 31;
    #pragma unroll
    for (int pass = 0; pass < 2; pass++) {
        int tt = pass*8 + wid;
        if (tt < 14) {
            int g = tt % 7, ch = tt / 7;
            int c0 = ch*64 + lane*2;
            float rb0 = b2v[c0], rb1_ = b2v[c0+1];
            u64 acc[2][4];
            #pragma unroll
            for (int ep = 0; ep < 4; ep++) { acc[0][ep] = pk2(rb0, rb0); acc[1][ep] = pk2(rb1_, rb1_); }
            const float* l1base = l1T + g*8;
            #pragma unroll 8
            for (int k = 0; k < 128; k++) {
                ulonglong2 Ea = *(const ulonglong2*)&l1base[k*56];        // edges 0..3 (broadcast)
                ulonglong2 Eb = *(const ulonglong2*)&l1base[k*56 + 4];    // edges 4..7
                u64 w01 = *(const u64*)&sW2T[k*130 + c0];
                float w0, w1; up2(w01, w0, w1);
                u64 w00 = pk2(w0, w0), w11 = pk2(w1, w1);
                fma2(acc[0][0], Ea.x, w00); fma2(acc[0][1], Ea.y, w00);
                fma2(acc[0][2], Eb.x, w00); fma2(acc[0][3], Eb.y, w00);
                fma2(acc[1][0], Ea.x, w11); fma2(acc[1][1], Ea.y, w11);
                fma2(acc[1][2], Eb.x, w11); fma2(acc[1][3], Eb.y, w11);
            }
            float w30a = W3[c0], w30b = W3[c0+1];
            float w31a = W3[HD+c0], w31b = W3[HD+c0+1];
            #pragma unroll
            for (int ep = 0; ep < 4; ep++) {
                float lA0, lB0, lA1, lB1;
                up2(acc[0][ep], lA0, lB0);
                up2(acc[1][ep], lA1, lB1);
                lA0 = fmaxf(lA0, 0.f); lB0 = fmaxf(lB0, 0.f);
                lA1 = fmaxf(lA1, 0.f); lB1 = fmaxf(lB1, 0.f);
                float pA0 = fmaf(lA1, w30b, lA0*w30a);
                float pA1 = fmaf(lA1, w31b, lA0*w31a);
                float pB0 = fmaf(lB1, w30b, lB0*w30a);
                float pB1 = fmaf(lB1, w31b, lB0*w31a);
                #pragma unroll
                for (int off = 16; off; off >>= 1) {
                    pA0 += __shfl_xor_sync(0xffffffffu, pA0, off);
                    pA1 += __shfl_xor_sync(0xffffffffu, pA1, off);
                    pB0 += __shfl_xor_sync(0xffffffffu, pB0, off);
                    pB1 += __shfl_xor_sync(0xffffffffu, pB1, off);
                }
                if (lane == 0) {
                    int baseI = g*32 + ch*16;
                    sPart[baseI + (2*ep)*2 + 0] = pA0;
                    sPart[baseI + (2*ep)*2 + 1] = pA1;
                    sPart[baseI + (2*ep+1)*2 + 0] = pB0;
                    sPart[baseI + (2*ep+1)*2 + 1] = pB1;
                }
            }
        }
    }
    __syncthreads();
    // ---- deterministic segment-sum
    if (t < 16) {
        int ii = t >> 1, c = t & 1;
        float s = 0.f;
        #pragma unroll
        for (int jj = 0; jj < 7; jj++) {
            int e = ii*7 + jj;
            int g = e >> 3, slot = e & 7;
            s += sPart[g*32 + slot*2 + c] + sPart[g*32 + 16 + slot*2 + c];
        }
        snm[ii*2 + c] = s;
    }
    // GRU weights overlay sW2T; sHv overlays sP
    float* sWhh = sm;            // [192][65]
    float* sWih = sm + 12480;    // 384
    float* sbih = sm + 12864;    // 192
    float* sbhh = sm + 13056;    // 192
    float* sHv  = sm + 16640;    // [8][65]
    for (int i4 = t; i4 < 3072; i4 += 256) {
        float4 w = ((const float4*)gWhh)[i4];
        int base = i4*4, q = base >> 6, k = base & 63;
        sWhh[q*65 + k + 0] = w.x;
        sWhh[q*65 + k + 1] = w.y;
        sWhh[q*65 + k + 2] = w.z;
        sWhh[q*65 + k + 3] = w.w;
    }
    for (int i4 = t; i4 < 96; i4 += 256) ((float4*)sWih)[i4] = ((const float4*)gWih)[i4];
    if (t < 192) { sbih[t] = gbih[t]; sbhh[t] = gbhh[t]; }
    for (int i4 = t; i4 < 128; i4 += 256) {
        int n = i4 >> 4, r = (i4 & 15) * 4;
        float4 h = ((const float4*)(g_hv + smIdx[n]*SD))[i4 & 15];
        sHv[n*65 + r + 0] = h.x;
        sHv[n*65 + r + 1] = h.y;
        sHv[n*65 + r + 2] = h.z;
        sHv[n*65 + r + 3] = h.w;
    }
    __syncthreads();
    float sb30 = 7.f*b3[0], sb31 = 7.f*b3[1];
    int nn = t >> 5, s0 = t & 31;
    float x0 = snm[nn*2] + sb30, x1 = snm[nn*2+1] + sb31;
    const float* hrow = sHv + nn*65;
    #pragma unroll
    for (int j2 = 0; j2 < 2; j2++) {
        int s = s0 + j2*32;
        float gir = fmaf(x1, sWih[2*s+1],       fmaf(x0, sWih[2*s],       sbih[s]));
        float giz = fmaf(x1, sWih[2*(64+s)+1],  fmaf(x0, sWih[2*(64+s)],  sbih[64+s]));
        float gin = fmaf(x1, sWih[2*(128+s)+1], fmaf(x0, sWih[2*(128+s)], sbih[128+s]));
        float ghr = sbhh[s], ghz = sbhh[64+s], ghn = sbhh[128+s];
        const float* wr = sWhh + s*65;
        const float* wz = sWhh + (64+s)*65;
        const float* wg = sWhh + (128+s)*65;
        #pragma unroll 8
        for (int k = 0; k < 64; k++) {
            float h = hrow[k];
            ghr = fmaf(h, wr[k], ghr);
            ghz = fmaf(h, wz[k], ghz);
            ghn = fmaf(h, wg[k], ghn);
        }
        float r  = sigm(gir + ghr);
        float z  = sigm(giz + ghz);
        float gg = tanh_fast(fmaf(r, ghn, gin));
        float h  = hrow[s];
        g_hv[smIdx[nn]*SD + s] = fmaf(z, h - gg, gg);
    }
}

// ---------------- K3: f2v MLP + logsumexp + GRU(h_f2v) ----------------
// smem floats: sW 16900 (pitch 130) | sXT 4680 | l1T 4608 | sAB 64 | sEm 64 | sNew 64 | sPart 128 = 26508
#define K3_SMEM (26508*4)
__global__ void __launch_bounds__(256) k3_f2v(
    const float* __restrict__ Jm, const float* __restrict__ W1, const float* __restrict__ b1v,
    const float* __restrict__ W2, const float* __restrict__ b2v,
    const float* __restrict__ W3, const float* __restrict__ b3,
    const float* __restrict__ gWih, const float* __restrict__ gWhh,
    const float* __restrict__ gbih, const float* __restrict__ gbhh,
    const float* __restrict__ bvec, const int* __restrict__ node_var)
{
    extern __shared__ float sm[];
    float* sW    = sm;           // W1T/W2T pitch 130 -> GRU weights
    float* sXT   = sm + 16900;   // [k 0..129][n 0..31] pitch 36
    float* l1T   = sm + 21580;   // [col 0..127][n 0..31] pitch 36
    float* sAB   = sm + 26188;
    float* sEm   = sm + 26252;
    float* sNew  = sm + 26316;
    float* sPart = sm + 26380;   // [ch][n 0..31][2]
    int t = threadIdx.x;
    int mb = blockIdx.x * 32;
    int wid = t >> 5, lane = t & 31;
    for (int i = t; i < 16640; i += 256) {
        int c = i / 130, k = i - c*130;
        sW[k*130 + c] = W1[i];
    }
    for (int i = t; i < 2048; i += 256) {
        int n = i >> 6, k = i & 63;
        sXT[k*36 + n]        = g_hv[(mb+n)*SD + k];
        sXT[(64+k)*36 + n]   = g_hf[(mb + (n^1))*SD + k];
    }
    if (t < 32) {
        int u = node_var[mb + t], vv = node_var[mb + (t^1)];
        sXT[128*36 + t] = bvec[u];
        sXT[129*36 + t] = bvec[vv];
        sAB[t*2]   = Jm[u*NV + vv];
        sAB[t*2+1] = Jm[vv*NV + u];
    }
    __syncthreads();
    // ---- layer1: 8 warp tasks (nodechunk, colhalf)
    {
        int nc = (wid & 3) * 8, ch = wid >> 2;
        int c0 = ch*64 + lane*2;
        float rb0 = b1v[c0], rb1_ = b1v[c0+1];
        u64 acc[2][4];
        #pragma unroll
        for (int np = 0; np < 4; np++) { acc[0][np] = pk2(rb0, rb0); acc[1][np] = pk2(rb1_, rb1_); }
        #pragma unroll 8
        for (int k = 0; k < 130; k++) {
            ulonglong2 Xa = *(const ulonglong2*)&sXT[k*36 + nc];
            ulonglong2 Xb = *(const ulonglong2*)&sXT[k*36 + nc + 4];
            u64 w01 = *(const u64*)&sW[k*130 + c0];
            float w0, w1; up2(w01, w0, w1);
            u64 w00 = pk2(w0, w0), w11 = pk2(w1, w1);
            fma2(acc[0][0], Xa.x, w00); fma2(acc[0][1], Xa.y, w00);
            fma2(acc[0][2], Xb.x, w00); fma2(acc[0][3], Xb.y, w00);
            fma2(acc[1][0], Xa.x, w11); fma2(acc[1][1], Xa.y, w11);
            fma2(acc[1][2], Xb.x, w11); fma2(acc[1][3], Xb.y, w11);
        }
        #pragma unroll
        for (int c = 0; c < 2; c++) {
            float v[8];
            #pragma unroll
            for (int np = 0; np < 4; np++) up2(acc[c][np], v[2*np], v[2*np+1]);
            #pragma unroll
            for (int j = 0; j < 8; j++) v[j] = fmaxf(v[j], 0.f);
            *(float4*)&l1T[(c0+c)*36 + nc]     = make_float4(v[0], v[1], v[2], v[3]);
            *(float4*)&l1T[(c0+c)*36 + nc + 4] = make_float4(v[4], v[5], v[6], v[7]);
        }
    }
    __syncthreads();
    for (int i4 = t; i4 < 4096; i4 += 256) {
        float4 w = ((const float4*)W2)[i4];
        int base = i4*4, cc = base >> 7, k = base & 127;
        sW[(k+0)*130 + cc] = w.x;
        sW[(k+1)*130 + cc] = w.y;
        sW[(k+2)*130 + cc] = w.z;
        sW[(k+3)*130 + cc] = w.w;
    }
    __syncthreads();
    // ---- layer2 + layer3
    {
        int nc = (wid & 3) * 8, ch = wid >> 2;
        int c0 = ch*64 + lane*2;
        float rb0 = b2v[c0], rb1_ = b2v[c0+1];
        u64 acc[2][4];
        #pragma unroll
        for (int np = 0; np < 4; np++) { acc[0][np] = pk2(rb0, rb0); acc[1][np] = pk2(rb1_, rb1_); }
        #pragma unroll 8
        for (int k = 0; k < 128; k++) {
            ulonglong2 La = *(const ulonglong2*)&l1T[k*36 + nc];
            ulonglong2 Lb = *(const ulonglong2*)&l1T[k*36 + nc + 4];
            u64 w01 = *(const u64*)&sW[k*130 + c0];
            float w0, w1; up2(w01, w0, w1);
            u64 w00 = pk2(w0, w0), w11 = pk2(w1, w1);
            fma2(acc[0][0], La.x, w00); fma2(acc[0][1], La.y, w00);
            fma2(acc[0][2], Lb.x, w00); fma2(acc[0][3], Lb.y, w00);
            fma2(acc[1][0], La.x, w11); fma2(acc[1][1], La.y, w11);
            fma2(acc[1][2], Lb.x, w11); fma2(acc[1][3], Lb.y, w11);
        }
        float w30a = W3[c0], w30b = W3[c0+1];
        float w31a = W3[HD+c0], w31b = W3[HD+c0+1];
        #pragma unroll
        for (int np = 0; np < 4; np++) {
            float lA0, lB0, lA1, lB1;
            up2(acc[0][np], lA0, lB0);
            up2(acc[1][np], lA1, lB1);
            lA0 = fmaxf(lA0, 0.f); lB0 = fmaxf(lB0, 0.f);
            lA1 = fmaxf(lA1, 0.f); lB1 = fmaxf(lB1, 0.f);
            float pA0 = fmaf(lA1, w30b, lA0*w30a);
            float pA1 = fmaf(lA1, w31b, lA0*w31a);
            float pB0 = fmaf(lB1, w30b, lB0*w30a);
            float pB1 = fmaf(lB1, w31b, lB0*w31a);
            #pragma unroll
            for (int off = 16; off; off >>= 1) {
                pA0 += __shfl_xor_sync(0xffffffffu, pA0, off);
                pA1 += __shfl_xor_sync(0xffffffffu, pA1, off);
                pB0 += __shfl_xor_sync(0xffffffffu, pB0, off);
                pB1 += __shfl_xor_sync(0xffffffffu, pB1, off);
            }
            if (lane == 0) {
                int nA = nc + 2*np, nB = nA + 1;
                sPart[ch*64 + nA*2 + 0] = pA0;
                sPart[ch*64 + nA*2 + 1] = pA1;
                sPart[ch*64 + nB*2 + 0] = pB0;
                sPart[ch*64 + nB*2 + 1] = pB1;
            }
        }
    }
    __syncthreads();
    if (t < 64) {
        int n = t >> 1, c = t & 1;
        sEm[n*2 + c] = sPart[n*2 + c] + sPart[64 + n*2 + c] + b3[c];
    }
    __syncthreads();
    // per-node logsumexp over 2x2 factor table
    if (t < 64) {
        int n = t >> 1, c = t & 1;
        float A = sAB[n*2], B = sAB[n*2+1];
        float em0 = sEm[n*2], em1 = sEm[n*2+1];
        float a = (c == 0) ? (A + B + em0) : (-2.f*A + em0);
        float d = (c == 0) ? (-2.f*B + em1) : (A + B + em1);
        float mx = fmaxf(a, d), mn = fminf(a, d);
        sNew[n*2 + c] = mx + log1pf(expf(mn - mx));
    }
    __syncthreads();
    // GRU(h_f2v), x = new[sib]; weights overlay sW
    float* sWih = sW + 12480; float* sbih = sW + 12864; float* sbhh = sW + 13056;
    for (int i4 = t; i4 < 3072; i4 += 256) {
        float4 w = ((const float4*)gWhh)[i4];
        int base = i4*4, q = base >> 6, k = base & 63;
        sW[q*65 + k + 0] = w.x;
        sW[q*65 + k + 1] = w.y;
        sW[q*65 + k + 2] = w.z;
        sW[q*65 + k + 3] = w.w;
    }
    for (int i4 = t; i4 < 96; i4 += 256) ((float4*)sWih)[i4] = ((const float4*)gWih)[i4];
    if (t < 192) { sbih[t] = gbih[t]; sbhh[t] = gbhh[t]; }
    __syncthreads();
    int nn = t >> 3, s0b = t & 7, sibl = nn ^ 1;
    float x0 = sNew[sibl*2], x1 = sNew[sibl*2 + 1];
    #pragma unroll
    for (int j2 = 0; j2 < 8; j2++) {
        int s = s0b + j2*8;
        float gir = fmaf(x1, sWih[2*s+1],       fmaf(x0, sWih[2*s],       sbih[s]));
        float giz = fmaf(x1, sWih[2*(64+s)+1],  fmaf(x0, sWih[2*(64+s)],  sbih[64+s]));
        float gin = fmaf(x1, sWih[2*(128+s)+1], fmaf(x0, sWih[2*(128+s)], sbih[128+s]));
        float ghr = sbhh[s], ghz = sbhh[64+s], ghn = sbhh[128+s];
        const float* wr = sW + s*65;
        const float* wz = sW + (64+s)*65;
        const float* wg = sW + (128+s)*65;
        #pragma unroll 8
        for (int k = 0; k < 64; k++) {
            float h = sXT[(64+k)*36 + sibl];   // == h_f2v[mb+nn][k]
            ghr = fmaf(h, wr[k], ghr);
            ghz = fmaf(h, wz[k], ghz);
            ghn = fmaf(h, wg[k], ghn);
        }
        float r  = sigm(gir + ghr);
        float z  = sigm(giz + ghz);
        float gg = tanh_fast(fmaf(r, ghn, gin));
        float h  = sXT[(64+s)*36 + sibl];
        g_hf[(mb+nn)*SD + s] = fmaf(z, h - gg, gg);
    }
}

// ---------------- K4: readout MLP + softmax ----------------
// smem floats: sW1 8256 | sW2 16512 | snm 64 | sh1 128 | sh2 128 | sp 8 = 25096
#define K4_SMEM (25096*4)
__global__ void __launch_bounds__(128) k4_readout(
    const float* __restrict__ W1, const float* __restrict__ b1,
    const float* __restrict__ W2, const float* __restrict__ b2,
    const float* __restrict__ W3, const float* __restrict__ b3,
    float* __restrict__ out)
{
    extern __shared__ float sm[];
    float* sW1 = sm;
    float* sW2 = sm + 8256;
    float* snm = sm + 24768;
    float* sh1 = sm + 24832;
    float* sh2 = sm + 24960;
    float* sp  = sm + 25088;
    int t = threadIdx.x, v = blockIdx.x;
    for (int i = t; i < 8192; i += 128)  { int c = i >> 6, k = i & 63;  sW1[k*129+c] = W1[i]; }
    for (int i = t; i < 16384; i += 128) { int c = i >> 7, k = i & 127; sW2[k*129+c] = W2[i]; }
    if (t < 64) {
        float s = 0.f;
        #pragma unroll
        for (int d = 0; d < 8; d++) s += g_hf[g_varlist[v*DEG + d]*SD + t];
        snm[t] = s;
    }
    __syncthreads();
    {
        float acc = b1[t];
        #pragma unroll 8
        for (int k = 0; k < 64; k++) acc = fmaf(snm[k], sW1[k*129 + t], acc);
        sh1[t] = fmaxf(acc, 0.f);
    }
    __syncthreads();
    {
        float acc = b2[t];
        #pragma unroll 8
        for (int k = 0; k < 128; k++) acc = fmaf(sh1[k], sW2[k*129 + t], acc);
        sh2[t] = fmaxf(acc, 0.f);
    }
    __syncthreads();
    float h2 = sh2[t];
    float p0 = h2 * W3[t], p1 = h2 * W3[128 + t];
    #pragma unroll
    for (int off = 16; off; off >>= 1) {
        p0 += __shfl_xor_sync(0xffffffffu, p0, off);
        p1 += __shfl_xor_sync(0xffffffffu, p1, off);
    }
    int wid = t >> 5;
    if ((t & 31) == 0) { sp[wid*2] = p0; sp[wid*2+1] = p1; }
    __syncthreads();
    if (t == 0) {
        float l0 = sp[0] + sp[2] + sp[4] + sp[6] + b3[0];
        float l1 = sp[1] + sp[3] + sp[5] + sp[7] + b3[1];
        float m = fmaxf(l0, l1);
        float e0 = expf(l0 - m), e1 = expf(l1 - m);
        float inv = 1.f / (e0 + e1);
        out[v*2]     = e0 * inv;
        out[v*2 + 1] = e1 * inv;
    }
}

// ---------------- launch ----------------
extern "C" void kernel_launch(void* const* d_in, const int* in_sizes, int n_in,
                              void* d_out, int out_size) {
    (void)in_sizes; (void)n_in; (void)out_size;
    const float* J        = (const float*)d_in[0];
    const float* b        = (const float*)d_in[1];
    const int*   node_var = (const int*)  d_in[2];
    // d_in[3], d_in[4] (e1_row, e1_col) intentionally unused (structure rebuilt on device)
    const float* v2f_W1 = (const float*)d_in[5];
    const float* v2f_b1 = (const float*)d_in[6];
    const float* v2f_W2 = (const float*)d_in[7];
    const float* v2f_b2 = (const float*)d_in[8];
    const float* v2f_W3 = (const float*)d_in[9];
    const float* v2f_b3 = (const float*)d_in[10];
    const float* f2v_W1 = (const float*)d_in[11];
    const float* f2v_b1 = (const float*)d_in[12];
    const float* f2v_W2 = (const float*)d_in[13];
    const float* f2v_b2 = (const float*)d_in[14];
    const float* f2v_W3 = (const float*)d_in[15];
    const float* f2v_b3 = (const float*)d_in[16];
    const float* gv_Wih = (const float*)d_in[17];
    const float* gv_Whh = (const float*)d_in[18];
    const float* gv_bih = (const float*)d_in[19];
    const float* gv_bhh = (const float*)d_in[20];
    const float* gf_Wih = (const float*)d_in[21];
    const float* gf_Whh = (const float*)d_in[22];
    const float* gf_bih = (const float*)d_in[23];
    const float* gf_bhh = (const float*)d_in[24];
    const float* ro_W1  = (const float*)d_in[25];
    const float* ro_b1  = (const float*)d_in[26];
    const float* ro_W2  = (const float*)d_in[27];
    const float* ro_b2  = (const float*)d_in[28];
    const float* ro_W3  = (const float*)d_in[29];
    const float* ro_b3  = (const float*)d_in[30];

    cudaFuncSetAttribute((const void*)k1_pq,      cudaFuncAttributeMaxDynamicSharedMemorySize, K1_SMEM);
    cudaFuncSetAttribute((const void*)k2_edges,   cudaFuncAttributeMaxDynamicSharedMemorySize, K2_SMEM);
    cudaFuncSetAttribute((const void*)k3_f2v,     cudaFuncAttributeMaxDynamicSharedMemorySize, K3_SMEM);
    cudaFuncSetAttribute((const void*)k4_readout, cudaFuncAttributeMaxDynamicSharedMemorySize, K4_SMEM);

    k_init_a<<<2048, 256>>>();
    k_init_b<<<32, 256>>>(node_var);
    k_init_c<<<4, 256>>>();
    for (int s = 0; s < NSTEPS; s++) {
        k1_pq<<<NM/16, 256, K1_SMEM>>>(v2f_W1, v2f_b1, b, node_var);
        k2_edges<<<NV, 256, K2_SMEM>>>(v2f_W2, v2f_b2, v2f_W3, v2f_b3,
                                       gv_Wih, gv_Whh, gv_bih, gv_bhh);
        k3_f2v<<<NM/32, 256, K3_SMEM>>>(J, f2v_W1, f2v_b1, f2v_W2, f2v_b2, f2v_W3, f2v_b3,
                                        gf_Wih, gf_Whh, gf_bih, gf_bhh, b, node_var);
    }
    k4_readout<<<NV, 128, K4_SMEM>>>(ro_W1, ro_b1, ro_W2, ro_b2, ro_W3, ro_b3, (float*)d_out);
}

// round 11
// speedup vs baseline: 1.5782x; 1.0929x over previous
#include <cuda_runtime.h>
#include <math.h>

#define NV 1024
#define NM 8192
#define DEG 8
#define SD 64
#define HD 128
#define NSTEPS 10

typedef unsigned long long u64;

__device__ __forceinline__ u64 pk2(float lo, float hi) {
    u64 r; asm("mov.b64 %0,{%1,%2};" : "=l"(r) : "f"(lo), "f"(hi)); return r;
}
__device__ __forceinline__ void up2(u64 v, float& lo, float& hi) {
    asm("mov.b64 {%0,%1},%2;" : "=f"(lo), "=f"(hi) : "l"(v));
}
__device__ __forceinline__ void fma2(u64& d, u64 a, u64 b) {
    asm("fma.rn.f32x2 %0,%1,%2,%0;" : "+l"(d) : "l"(a), "l"(b));
}

// ---------------- persistent device state ----------------
__device__ float g_hv[NM*SD];     // h_v2f
__device__ float g_hf[NM*SD];     // h_f2v
__device__ float g_P [NM*HD];
__device__ float g_Q [NM*HD];
__device__ int   g_varlist[NV*DEG];
__device__ int   g_cnt[NV];
// pre-transposed weights (smem-layout-exact, filled once by k_prep)
__device__ float g_W1Tv[129*128];
__device__ float g_W2Tv[128*128];
__device__ float g_W1Tf[130*128];
__device__ float g_W2Tf[128*128];
__device__ float g_WhhV[192*65];
__device__ float g_WhhF[192*65];

__device__ __forceinline__ float sigm(float x) {
    return __fdividef(1.f, 1.f + __expf(-x));
}
__device__ __forceinline__ float tanh_fast(float x) {
    return 1.f - __fdividef(2.f, __expf(2.f*x) + 1.f);
}

// ---------------- init ----------------
__global__ void k_init_a() {
    int idx = blockIdx.x*blockDim.x + threadIdx.x;
    if (idx < NV) g_cnt[idx] = 0;
    if (idx < NM*SD) { g_hv[idx] = 0.f; g_hf[idx] = 0.f; }
}
__global__ void k_init_b(const int* __restrict__ node_var) {
    int m = blockIdx.x*blockDim.x + threadIdx.x;
    if (m >= NM) return;
    int u = node_var[m];
    int pos = atomicAdd(&g_cnt[u], 1);
    g_varlist[u*DEG + pos] = m;
}
__global__ void k_init_c() {
    int v = blockIdx.x*blockDim.x + threadIdx.x;
    if (v >= NV) return;
    int* p = &g_varlist[v*DEG];
    for (int a = 1; a < DEG; a++) {
        int key = p[a]; int b = a - 1;
        while (b >= 0 && p[b] > key) { p[b+1] = p[b]; b--; }
        p[b+1] = key;
    }
}
// one-time weight pre-transposition
__global__ void k_prep(const float* __restrict__ W1v, const float* __restrict__ W2v,
                       const float* __restrict__ W1f, const float* __restrict__ W2f,
                       const float* __restrict__ WhhV, const float* __restrict__ WhhF)
{
    int i = blockIdx.x*blockDim.x + threadIdx.x;
    if (i < 16512) { int c = i / 129, k = i - c*129; g_W1Tv[k*128 + c] = W1v[i]; }
    if (i < 16384) { int c = i >> 7,  k = i & 127;  g_W2Tv[k*128 + c] = W2v[i]; }
    if (i < 16640) { int c = i / 130, k = i - c*130; g_W1Tf[k*128 + c] = W1f[i]; }
    if (i < 16384) { int c = i >> 7,  k = i & 127;  g_W2Tf[k*128 + c] = W2f[i]; }
    if (i < 12288) { int q = i >> 6,  k = i & 63;   g_WhhV[q*65 + k] = WhhV[i];
                                                    g_WhhF[q*65 + k] = WhhF[i]; }
    if (i < 192)   { g_WhhV[i*65 + 64] = 0.f; g_WhhF[i*65 + 64] = 0.f; }
}

// ---------------- K1: P/Q precompute, 32 nodes/block ----------------
// smem floats: sW1T 16512 (pitch 128) | shf 64*36 | shv 64*36 | sbv 32 = 21152 (84.6KB)
#define K1_SMEM (21152*4)
__global__ void __launch_bounds__(256, 2) k1_pq(
    const float* __restrict__ b1,
    const float* __restrict__ bvec, const int* __restrict__ node_var)
{
    extern __shared__ float sm[];
    float* sW1T = sm;            // [k 0..128][c 0..127] pitch 128
    float* shf  = sm + 16512;    // [k 0..63][n 0..31] pitch 36
    float* shv  = sm + 18816;
    float* sbv  = sm + 21120;
    int t = threadIdx.x;
    int mb = blockIdx.x * 32;
    for (int i4 = t; i4 < 4128; i4 += 256)
        ((float4*)sW1T)[i4] = ((const float4*)g_W1Tv)[i4];
    for (int i = t; i < 2048; i += 256) {
        int n = i >> 6, k = i & 63;
        shf[k*36 + n] = g_hf[(mb+n)*SD + k];
        shv[k*36 + n] = g_hv[(mb+n)*SD + k];
    }
    if (t < 32) sbv[t] = bvec[node_var[mb + t]];
    __syncthreads();
    int wid = t >> 5, lane = t & 31;
    #pragma unroll
    for (int iter = 0; iter < 2; iter++) {   // 0 = P (hf, W1a), 1 = Q (hv, W1b + bias)
        const float* hT = iter ? shv : shf;
        float* dst = iter ? g_Q : g_P;
        int kofs = iter ? 64 : 0;
        #pragma unroll
        for (int rep = 0; rep < 2; rep++) {
            int task = rep*8 + wid;          // 0..15
            int quad = task & 7, ch = task >> 3;
            int nq = quad*4, c0 = ch*64 + lane*2;
            u64 a0a, a0b, a1a, a1b;
            if (iter) {
                float wl0 = sW1T[128*128 + c0], wl1 = sW1T[128*128 + c0 + 1];
                float rb0 = b1[c0], rb1_ = b1[c0+1];
                float bA = sbv[nq], bB = sbv[nq+1], bC = sbv[nq+2], bD = sbv[nq+3];
                a0a = pk2(fmaf(bA, wl0, rb0),  fmaf(bB, wl0, rb0));
                a0b = pk2(fmaf(bC, wl0, rb0),  fmaf(bD, wl0, rb0));
                a1a = pk2(fmaf(bA, wl1, rb1_), fmaf(bB, wl1, rb1_));
                a1b = pk2(fmaf(bC, wl1, rb1_), fmaf(bD, wl1, rb1_));
            } else { a0a = a0b = a1a = a1b = 0ULL; }
            #pragma unroll 8
            for (int k = 0; k < 64; k++) {
                ulonglong2 h2 = *(const ulonglong2*)&hT[k*36 + nq];   // 4 nodes, broadcast
                u64 w01 = *(const u64*)&sW1T[(k + kofs)*128 + c0];
                float w0, w1; up2(w01, w0, w1);
                u64 w00 = pk2(w0, w0), w11 = pk2(w1, w1);
                fma2(a0a, h2.x, w00); fma2(a0b, h2.y, w00);
                fma2(a1a, h2.x, w11); fma2(a1b, h2.y, w11);
            }
            float A0, B0, C0, D0, A1, B1, C1, D1;
            up2(a0a, A0, B0); up2(a0b, C0, D0);
            up2(a1a, A1, B1); up2(a1b, C1, D1);
            *(float2*)&dst[(mb+nq+0)*HD + c0] = make_float2(A0, A1);
            *(float2*)&dst[(mb+nq+1)*HD + c0] = make_float2(B0, B1);
            *(float2*)&dst[(mb+nq+2)*HD + c0] = make_float2(C0, C1);
            *(float2*)&dst[(mb+nq+3)*HD + c0] = make_float2(D0, D1);
        }
    }
}

// ---------------- K2: per-variable edge MLP + segsum + GRU(h_v2f) -------
// smem floats: sW2T 16384 | sP 1024 | sQ 1024 | l1T 7168 | sPart 256 | snm 16 = 25872
#define K2_SMEM (25872*4)
__global__ void __launch_bounds__(256) k2_edges(
    const float* __restrict__ b2v,
    const float* __restrict__ W3, const float* __restrict__ b3,
    const float* __restrict__ gWih,
    const float* __restrict__ gbih, const float* __restrict__ gbhh)
{
    extern __shared__ float sm[];
    __shared__ int smIdx[8];
    float* sW2T  = sm;           // [k][c] pitch 128
    float* sP    = sm + 16384;
    float* sQ    = sm + 17408;
    float* l1T   = sm + 18432;   // [col 0..127][edge 0..55] pitch 56
    float* sPart = sm + 25600;   // [g 0..6][ch 0..1][e 0..7][2]
    float* snm   = sm + 25856;   // [8][2]
    int t = threadIdx.x, v = blockIdx.x;
    if (t < 8) smIdx[t] = g_varlist[v*DEG + t];
    for (int i4 = t; i4 < 4096; i4 += 256)
        ((float4*)sW2T)[i4] = ((const float4*)g_W2Tv)[i4];
    __syncthreads();   // smIdx visible
    for (int i = t; i < 256; i += 256) {
        int n = i >> 5, f = i & 31;
        ((float4*)sP)[i] = ((const float4*)(g_P + smIdx[n]*HD))[f];
        ((float4*)sQ)[i] = ((const float4*)(g_Q + smIdx[n]*HD))[f];
    }
    __syncthreads();
    // ---- stage all 56 edges' layer-1
    {
        int col = t & 127, e0 = (t >> 7) * 4;
        #pragma unroll
        for (int g = 0; g < 7; g++) {
            int be = g*8 + e0;
            float l1v[4];
            #pragma unroll
            for (int q = 0; q < 4; q++) {
                int e = be + q, ii = e/7, jj = e - ii*7;
                int j = jj + (jj >= ii);
                l1v[q] = fmaxf(sP[j*HD + col] + sQ[ii*HD + col], 0.f);
            }
            *(float4*)&l1T[col*56 + be] = make_float4(l1v[0], l1v[1], l1v[2], l1v[3]);
        }
    }
    __syncthreads();
    // ---- layer2+layer3: warp tasks (g, colhalf), 2 passes
    int wid = t >> 5, lane = t & 31;
    #pragma unroll
    for (int pass = 0; pass < 2; pass++) {
        int tt = pass*8 + wid;
        if (tt < 14) {
            int g = tt % 7, ch = tt / 7;
            int c0 = ch*64 + lane*2;
            float rb0 = b2v[c0], rb1_ = b2v[c0+1];
            u64 acc[2][4];
            #pragma unroll
            for (int ep = 0; ep < 4; ep++) { acc[0][ep] = pk2(rb0, rb0); acc[1][ep] = pk2(rb1_, rb1_); }
            const float* l1base = l1T + g*8;
            #pragma unroll 8
            for (int k = 0; k < 128; k++) {
                ulonglong2 Ea = *(const ulonglong2*)&l1base[k*56];        // edges 0..3 (broadcast)
                ulonglong2 Eb = *(const ulonglong2*)&l1base[k*56 + 4];    // edges 4..7
                u64 w01 = *(const u64*)&sW2T[k*128 + c0];
                float w0, w1; up2(w01, w0, w1);
                u64 w00 = pk2(w0, w0), w11 = pk2(w1, w1);
                fma2(acc[0][0], Ea.x, w00); fma2(acc[0][1], Ea.y, w00);
                fma2(acc[0][2], Eb.x, w00); fma2(acc[0][3], Eb.y, w00);
                fma2(acc[1][0], Ea.x, w11); fma2(acc[1][1], Ea.y, w11);
                fma2(acc[1][2], Eb.x, w11); fma2(acc[1][3], Eb.y, w11);
            }
            float w30a = W3[c0], w30b = W3[c0+1];
            float w31a = W3[HD+c0], w31b = W3[HD+c0+1];
            #pragma unroll
            for (int ep = 0; ep < 4; ep++) {
                float lA0, lB0, lA1, lB1;
                up2(acc[0][ep], lA0, lB0);
                up2(acc[1][ep], lA1, lB1);
                lA0 = fmaxf(lA0, 0.f); lB0 = fmaxf(lB0, 0.f);
                lA1 = fmaxf(lA1, 0.f); lB1 = fmaxf(lB1, 0.f);
                float pA0 = fmaf(lA1, w30b, lA0*w30a);
                float pA1 = fmaf(lA1, w31b, lA0*w31a);
                float pB0 = fmaf(lB1, w30b, lB0*w30a);
                float pB1 = fmaf(lB1, w31b, lB0*w31a);
                #pragma unroll
                for (int off = 16; off; off >>= 1) {
                    pA0 += __shfl_xor_sync(0xffffffffu, pA0, off);
                    pA1 += __shfl_xor_sync(0xffffffffu, pA1, off);
                    pB0 += __shfl_xor_sync(0xffffffffu, pB0, off);
                    pB1 += __shfl_xor_sync(0xffffffffu, pB1, off);
                }
                if (lane == 0) {
                    int baseI = g*32 + ch*16;
                    sPart[baseI + (2*ep)*2 + 0] = pA0;
                    sPart[baseI + (2*ep)*2 + 1] = pA1;
                    sPart[baseI + (2*ep+1)*2 + 0] = pB0;
                    sPart[baseI + (2*ep+1)*2 + 1] = pB1;
                }
            }
        }
    }
    __syncthreads();
    // ---- deterministic segment-sum
    if (t < 16) {
        int ii = t >> 1, c = t & 1;
        float s = 0.f;
        #pragma unroll
        for (int jj = 0; jj < 7; jj++) {
            int e = ii*7 + jj;
            int g = e >> 3, slot = e & 7;
            s += sPart[g*32 + slot*2 + c] + sPart[g*32 + 16 + slot*2 + c];
        }
        snm[ii*2 + c] = s;
    }
    // GRU weights overlay sW2T; sHv overlays sP
    float* sWhh = sm;            // [192][65]
    float* sWih = sm + 12480;    // 384
    float* sbih = sm + 12864;    // 192
    float* sbhh = sm + 13056;    // 192
    float* sHv  = sm + 16384;    // [8][65]
    for (int i4 = t; i4 < 3120; i4 += 256)
        ((float4*)sWhh)[i4] = ((const float4*)g_WhhV)[i4];
    for (int i4 = t; i4 < 96; i4 += 256) ((float4*)sWih)[i4] = ((const float4*)gWih)[i4];
    if (t < 192) { sbih[t] = gbih[t]; sbhh[t] = gbhh[t]; }
    for (int i4 = t; i4 < 128; i4 += 256) {
        int n = i4 >> 4, r = (i4 & 15) * 4;
        float4 h = ((const float4*)(g_hv + smIdx[n]*SD))[i4 & 15];
        sHv[n*65 + r + 0] = h.x;
        sHv[n*65 + r + 1] = h.y;
        sHv[n*65 + r + 2] = h.z;
        sHv[n*65 + r + 3] = h.w;
    }
    __syncthreads();
    float sb30 = 7.f*b3[0], sb31 = 7.f*b3[1];
    int nn = t >> 5, s0 = t & 31;
    float x0 = snm[nn*2] + sb30, x1 = snm[nn*2+1] + sb31;
    const float* hrow = sHv + nn*65;
    #pragma unroll
    for (int j2 = 0; j2 < 2; j2++) {
        int s = s0 + j2*32;
        float gir = fmaf(x1, sWih[2*s+1],       fmaf(x0, sWih[2*s],       sbih[s]));
        float giz = fmaf(x1, sWih[2*(64+s)+1],  fmaf(x0, sWih[2*(64+s)],  sbih[64+s]));
        float gin = fmaf(x1, sWih[2*(128+s)+1], fmaf(x0, sWih[2*(128+s)], sbih[128+s]));
        float ghr = sbhh[s], ghz = sbhh[64+s], ghn = sbhh[128+s];
        const float* wr = sWhh + s*65;
        const float* wz = sWhh + (64+s)*65;
        const float* wg = sWhh + (128+s)*65;
        #pragma unroll 8
        for (int k = 0; k < 64; k++) {
            float h = hrow[k];
            ghr = fmaf(h, wr[k], ghr);
            ghz = fmaf(h, wz[k], ghz);
            ghn = fmaf(h, wg[k], ghn);
        }
        float r  = sigm(gir + ghr);
        float z  = sigm(giz + ghz);
        float gg = tanh_fast(fmaf(r, ghn, gin));
        float h  = hrow[s];
        g_hv[smIdx[nn]*SD + s] = fmaf(z, h - gg, gg);
    }
}

// ---------------- K3: f2v MLP + logsumexp + GRU(h_f2v) ----------------
// smem floats: sW 16640 | sXT 4680 | l1T 4608 | sAB 64 | sEm 64 | sNew 64 | sPart 128 = 26248
#define K3_SMEM (26248*4)
__global__ void __launch_bounds__(256) k3_f2v(
    const float* __restrict__ Jm, const float* __restrict__ b1v,
    const float* __restrict__ b2v,
    const float* __restrict__ W3, const float* __restrict__ b3,
    const float* __restrict__ gWih,
    const float* __restrict__ gbih, const float* __restrict__ gbhh,
    const float* __restrict__ bvec, const int* __restrict__ node_var)
{
    extern __shared__ float sm[];
    float* sW    = sm;           // W1T/W2T pitch 128 -> GRU weights
    float* sXT   = sm + 16640;   // [k 0..129][n 0..31] pitch 36
    float* l1T   = sm + 21320;   // [col 0..127][n 0..31] pitch 36
    float* sAB   = sm + 25928;
    float* sEm   = sm + 25992;
    float* sNew  = sm + 26056;
    float* sPart = sm + 26120;   // [ch][n 0..31][2]
    int t = threadIdx.x;
    int mb = blockIdx.x * 32;
    int wid = t >> 5, lane = t & 31;
    for (int i4 = t; i4 < 4160; i4 += 256)
        ((float4*)sW)[i4] = ((const float4*)g_W1Tf)[i4];
    for (int i = t; i < 2048; i += 256) {
        int n = i >> 6, k = i & 63;
        sXT[k*36 + n]        = g_hv[(mb+n)*SD + k];
        sXT[(64+k)*36 + n]   = g_hf[(mb + (n^1))*SD + k];
    }
    if (t < 32) {
        int u = node_var[mb + t], vv = node_var[mb + (t^1)];
        sXT[128*36 + t] = bvec[u];
        sXT[129*36 + t] = bvec[vv];
        sAB[t*2]   = Jm[u*NV + vv];
        sAB[t*2+1] = Jm[vv*NV + u];
    }
    __syncthreads();
    // ---- layer1: 8 warp tasks (nodechunk, colhalf)
    {
        int nc = (wid & 3) * 8, ch = wid >> 2;
        int c0 = ch*64 + lane*2;
        float rb0 = b1v[c0], rb1_ = b1v[c0+1];
        u64 acc[2][4];
        #pragma unroll
        for (int np = 0; np < 4; np++) { acc[0][np] = pk2(rb0, rb0); acc[1][np] = pk2(rb1_, rb1_); }
        #pragma unroll 8
        for (int k = 0; k < 130; k++) {
            ulonglong2 Xa = *(const ulonglong2*)&sXT[k*36 + nc];
            ulonglong2 Xb = *(const ulonglong2*)&sXT[k*36 + nc + 4];
            u64 w01 = *(const u64*)&sW[k*128 + c0];
            float w0, w1; up2(w01, w0, w1);
            u64 w00 = pk2(w0, w0), w11 = pk2(w1, w1);
            fma2(acc[0][0], Xa.x, w00); fma2(acc[0][1], Xa.y, w00);
            fma2(acc[0][2], Xb.x, w00); fma2(acc[0][3], Xb.y, w00);
            fma2(acc[1][0], Xa.x, w11); fma2(acc[1][1], Xa.y, w11);
            fma2(acc[1][2], Xb.x, w11); fma2(acc[1][3], Xb.y, w11);
        }
        #pragma unroll
        for (int c = 0; c < 2; c++) {
            float v[8];
            #pragma unroll
            for (int np = 0; np < 4; np++) up2(acc[c][np], v[2*np], v[2*np+1]);
            #pragma unroll
            for (int j = 0; j < 8; j++) v[j] = fmaxf(v[j], 0.f);
            *(float4*)&l1T[(c0+c)*36 + nc]     = make_float4(v[0], v[1], v[2], v[3]);
            *(float4*)&l1T[(c0+c)*36 + nc + 4] = make_float4(v[4], v[5], v[6], v[7]);
        }
    }
    __syncthreads();
    for (int i4 = t; i4 < 4096; i4 += 256)
        ((float4*)sW)[i4] = ((const float4*)g_W2Tf)[i4];
    __syncthreads();
    // ---- layer2 + layer3
    {
        int nc = (wid & 3) * 8, ch = wid >> 2;
        int c0 = ch*64 + lane*2;
        float rb0 = b2v[c0], rb1_ = b2v[c0+1];
        u64 acc[2][4];
        #pragma unroll
        for (int np = 0; np < 4; np++) { acc[0][np] = pk2(rb0, rb0); acc[1][np] = pk2(rb1_, rb1_); }
        #pragma unroll 8
        for (int k = 0; k < 128; k++) {
            ulonglong2 La = *(const ulonglong2*)&l1T[k*36 + nc];
            ulonglong2 Lb = *(const ulonglong2*)&l1T[k*36 + nc + 4];
            u64 w01 = *(const u64*)&sW[k*128 + c0];
            float w0, w1; up2(w01, w0, w1);
            u64 w00 = pk2(w0, w0), w11 = pk2(w1, w1);
            fma2(acc[0][0], La.x, w00); fma2(acc[0][1], La.y, w00);
            fma2(acc[0][2], Lb.x, w00); fma2(acc[0][3], Lb.y, w00);
            fma2(acc[1][0], La.x, w11); fma2(acc[1][1], La.y, w11);
            fma2(acc[1][2], Lb.x, w11); fma2(acc[1][3], Lb.y, w11);
        }
        float w30a = W3[c0], w30b = W3[c0+1];
        float w31a = W3[HD+c0], w31b = W3[HD+c0+1];
        #pragma unroll
        for (int np = 0; np < 4; np++) {
            float lA0, lB0, lA1, lB1;
            up2(acc[0][np], lA0, lB0);
            up2(acc[1][np], lA1, lB1);
            lA0 = fmaxf(lA0, 0.f); lB0 = fmaxf(lB0, 0.f);
            lA1 = fmaxf(lA1, 0.f); lB1 = fmaxf(lB1, 0.f);
            float pA0 = fmaf(lA1, w30b, lA0*w30a);
            float pA1 = fmaf(lA1, w31b, lA0*w31a);
            float pB0 = fmaf(lB1, w30b, lB0*w30a);
            float pB1 = fmaf(lB1, w31b, lB0*w31a);
            #pragma unroll
            for (int off = 16; off; off >>= 1) {
                pA0 += __shfl_xor_sync(0xffffffffu, pA0, off);
                pA1 += __shfl_xor_sync(0xffffffffu, pA1, off);
                pB0 += __shfl_xor_sync(0xffffffffu, pB0, off);
                pB1 += __shfl_xor_sync(0xffffffffu, pB1, off);
            }
            if (lane == 0) {
                int nA = nc + 2*np, nB = nA + 1;
                sPart[ch*64 + nA*2 + 0] = pA0;
                sPart[ch*64 + nA*2 + 1] = pA1;
                sPart[ch*64 + nB*2 + 0] = pB0;
                sPart[ch*64 + nB*2 + 1] = pB1;
            }
        }
    }
    __syncthreads();
    if (t < 64) {
        int n = t >> 1, c = t & 1;
        sEm[n*2 + c] = sPart[n*2 + c] + sPart[64 + n*2 + c] + b3[c];
    }
    __syncthreads();
    // per-node logsumexp over 2x2 factor table
    if (t < 64) {
        int n = t >> 1, c = t & 1;
        float A = sAB[n*2], B = sAB[n*2+1];
        float em0 = sEm[n*2], em1 = sEm[n*2+1];
        float a = (c == 0) ? (A + B + em0) : (-2.f*A + em0);
        float d = (c == 0) ? (-2.f*B + em1) : (A + B + em1);
        float mx = fmaxf(a, d), mn = fminf(a, d);
        sNew[n*2 + c] = mx + log1pf(expf(mn - mx));
    }
    __syncthreads();
    // GRU(h_f2v), x = new[sib]; weights overlay sW
    float* sWih = sW + 12480; float* sbih = sW + 12864; float* sbhh = sW + 13056;
    for (int i4 = t; i4 < 3120; i4 += 256)
        ((float4*)sW)[i4] = ((const float4*)g_WhhF)[i4];
    for (int i4 = t; i4 < 96; i4 += 256) ((float4*)sWih)[i4] = ((const float4*)gWih)[i4];
    if (t < 192) { sbih[t] = gbih[t]; sbhh[t] = gbhh[t]; }
    __syncthreads();
    int nn = t >> 3, s0b = t & 7, sibl = nn ^ 1;
    float x0 = sNew[sibl*2], x1 = sNew[sibl*2 + 1];
    #pragma unroll
    for (int j2 = 0; j2 < 8; j2++) {
        int s = s0b + j2*8;
        float gir = fmaf(x1, sWih[2*s+1],       fmaf(x0, sWih[2*s],       sbih[s]));
        float giz = fmaf(x1, sWih[2*(64+s)+1],  fmaf(x0, sWih[2*(64+s)],  sbih[64+s]));
        float gin = fmaf(x1, sWih[2*(128+s)+1], fmaf(x0, sWih[2*(128+s)], sbih[128+s]));
        float ghr = sbhh[s], ghz = sbhh[64+s], ghn = sbhh[128+s];
        const float* wr = sW + s*65;
        const float* wz = sW + (64+s)*65;
        const float* wg = sW + (128+s)*65;
        #pragma unroll 8
        for (int k = 0; k < 64; k++) {
            float h = sXT[(64+k)*36 + sibl];   // == h_f2v[mb+nn][k]
            ghr = fmaf(h, wr[k], ghr);
            ghz = fmaf(h, wz[k], ghz);
            ghn = fmaf(h, wg[k], ghn);
        }
        float r  = sigm(gir + ghr);
        float z  = sigm(giz + ghz);
        float gg = tanh_fast(fmaf(r, ghn, gin));
        float h  = sXT[(64+s)*36 + sibl];
        g_hf[(mb+nn)*SD + s] = fmaf(z, h - gg, gg);
    }
}

// ---------------- K4: readout MLP + softmax ----------------
// smem floats: sW1 8256 | sW2 16512 | snm 64 | sh1 128 | sh2 128 | sp 8 = 25096
#define K4_SMEM (25096*4)
__global__ void __launch_bounds__(128) k4_readout(
    const float* __restrict__ W1, const float* __restrict__ b1,
    const float* __restrict__ W2, const float* __restrict__ b2,
    const float* __restrict__ W3, const float* __restrict__ b3,
    float* __restrict__ out)
{
    extern __shared__ float sm[];
    float* sW1 = sm;
    float* sW2 = sm + 8256;
    float* snm = sm + 24768;
    float* sh1 = sm + 24832;
    float* sh2 = sm + 24960;
    float* sp  = sm + 25088;
    int t = threadIdx.x, v = blockIdx.x;
    for (int i = t; i < 8192; i += 128)  { int c = i >> 6, k = i & 63;  sW1[k*129+c] = W1[i]; }
    for (int i = t; i < 16384; i += 128) { int c = i >> 7, k = i & 127; sW2[k*129+c] = W2[i]; }
    if (t < 64) {
        float s = 0.f;
        #pragma unroll
        for (int d = 0; d < 8; d++) s += g_hf[g_varlist[v*DEG + d]*SD + t];
        snm[t] = s;
    }
    __syncthreads();
    {
        float acc = b1[t];
        #pragma unroll 8
        for (int k = 0; k < 64; k++) acc = fmaf(snm[k], sW1[k*129 + t], acc);
        sh1[t] = fmaxf(acc, 0.f);
    }
    __syncthreads();
    {
        float acc = b2[t];
        #pragma unroll 8
        for (int k = 0; k < 128; k++) acc = fmaf(sh1[k], sW2[k*129 + t], acc);
        sh2[t] = fmaxf(acc, 0.f);
    }
    __syncthreads();
    float h2 = sh2[t];
    float p0 = h2 * W3[t], p1 = h2 * W3[128 + t];
    #pragma unroll
    for (int off = 16; off; off >>= 1) {
        p0 += __shfl_xor_sync(0xffffffffu, p0, off);
        p1 += __shfl_xor_sync(0xffffffffu, p1, off);
    }
    int wid = t >> 5;
    if ((t & 31) == 0) { sp[wid*2] = p0; sp[wid*2+1] = p1; }
    __syncthreads();
    if (t == 0) {
        float l0 = sp[0] + sp[2] + sp[4] + sp[6] + b3[0];
        float l1 = sp[1] + sp[3] + sp[5] + sp[7] + b3[1];
        float m = fmaxf(l0, l1);
        float e0 = expf(l0 - m), e1 = expf(l1 - m);
        float inv = 1.f / (e0 + e1);
        out[v*2]     = e0 * inv;
        out[v*2 + 1] = e1 * inv;
    }
}

// ---------------- launch ----------------
extern "C" void kernel_launch(void* const* d_in, const int* in_sizes, int n_in,
                              void* d_out, int out_size) {
    (void)in_sizes; (void)n_in; (void)out_size;
    const float* J        = (const float*)d_in[0];
    const float* b        = (const float*)d_in[1];
    const int*   node_var = (const int*)  d_in[2];
    // d_in[3], d_in[4] (e1_row, e1_col) intentionally unused (structure rebuilt on device)
    const float* v2f_W1 = (const float*)d_in[5];
    const float* v2f_b1 = (const float*)d_in[6];
    const float* v2f_W2 = (const float*)d_in[7];
    const float* v2f_b2 = (const float*)d_in[8];
    const float* v2f_W3 = (const float*)d_in[9];
    const float* v2f_b3 = (const float*)d_in[10];
    const float* f2v_W1 = (const float*)d_in[11];
    const float* f2v_b1 = (const float*)d_in[12];
    const float* f2v_W2 = (const float*)d_in[13];
    const float* f2v_b2 = (const float*)d_in[14];
    const float* f2v_W3 = (const float*)d_in[15];
    const float* f2v_b3 = (const float*)d_in[16];
    const float* gv_Wih = (const float*)d_in[17];
    const float* gv_Whh = (const float*)d_in[18];
    const float* gv_bih = (const float*)d_in[19];
    const float* gv_bhh = (const float*)d_in[20];
    const float* gf_Wih = (const float*)d_in[21];
    const float* gf_Whh = (const float*)d_in[22];
    const float* gf_bih = (const float*)d_in[23];
    const float* gf_bhh = (const float*)d_in[24];
    const float* ro_W1  = (const float*)d_in[25];
    const float* ro_b1  = (const float*)d_in[26];
    const float* ro_W2  = (const float*)d_in[27];
    const float* ro_b2  = (const float*)d_in[28];
    const float* ro_W3  = (const float*)d_in[29];
    const float* ro_b3  = (const float*)d_in[30];

    cudaFuncSetAttribute((const void*)k1_pq,      cudaFuncAttributeMaxDynamicSharedMemorySize, K1_SMEM);
    cudaFuncSetAttribute((const void*)k2_edges,   cudaFuncAttributeMaxDynamicSharedMemorySize, K2_SMEM);
    cudaFuncSetAttribute((const void*)k3_f2v,     cudaFuncAttributeMaxDynamicSharedMemorySize, K3_SMEM);
    cudaFuncSetAttribute((const void*)k4_readout, cudaFuncAttributeMaxDynamicSharedMemorySize, K4_SMEM);

    k_init_a<<<2048, 256>>>();
    k_init_b<<<32, 256>>>(node_var);
    k_init_c<<<4, 256>>>();
    k_prep<<<65, 256>>>(v2f_W1, v2f_W2, f2v_W1, f2v_W2, gv_Whh, gf_Whh);
    for (int s = 0; s < NSTEPS; s++) {
        k1_pq<<<NM/32, 256, K1_SMEM>>>(v2f_b1, b, node_var);
        k2_edges<<<NV, 256, K2_SMEM>>>(v2f_b2, v2f_W3, v2f_b3,
                                       gv_Wih, gv_bih, gv_bhh);
        k3_f2v<<<NM/32, 256, K3_SMEM>>>(J, f2v_b1, f2v_b2, f2v_W3, f2v_b3,
                                        gf_Wih, gf_bih, gf_bhh, b, node_var);
    }
    k4_readout<<<NV, 128, K4_SMEM>>>(ro_W1, ro_b1, ro_W2, ro_b2, ro_W3, ro_b3, (float*)d_out);
}